// round 11
// baseline (speedup 1.0000x reference)
#include <cuda_runtime.h>
#include <cuda_fp16.h>
#include <math.h>
#include <stdint.h>

#define B_  32
#define T_  384
#define D_  512
#define H_  16
#define BTD (B_*T_*D_)     // 6291456
#define M_  (B_*T_)        // 12288
#define WKN (512*512)

// ---------------- scratch (static device globals; no cudaMalloc) ----------
__device__ float g_xr[BTD], g_t1[BTD], g_t2[BTD], g_a1[BTD];
__device__ __half g_qh[BTD], g_ql[BTD], g_kh[BTD], g_kl[BTD], g_vh[BTD], g_vl[BTD];
__device__ __half g_q2h[BTD], g_q2l[BTD], g_k2h[BTD], g_k2l[BTD], g_v2h[BTD], g_v2l[BTD];
__device__ __half g_xh[BTD],  g_xl[BTD];
__device__ __half g_lnh[BTD], g_lnl[BTD];
__device__ __half g_dh[BTD],  g_dl[BTD];
__device__ __half g_wh[16*WKN], g_wl[16*WKN];   // [qw0-4 | kw0-4 | vw0-4 | fw]

// ---------------- helpers --------------------------------------------------
__device__ __forceinline__ void split_h(float x, __half& hi, __half& lo) {
    hi = __float2half_rn(x);
    lo = __float2half_rn(x - __half2float(hi));
}
__device__ __forceinline__ unsigned pack2(__half a, __half b) {
    __half2 h = __halves2half2(a, b);
    return *reinterpret_cast<unsigned*>(&h);
}
// NOTE: non-volatile — lets ptxas schedule HMMAs across independent
// accumulators (the volatile version pinned dependent 3-chains at distance 1).
__device__ __forceinline__ void mma_f16(float* c, const unsigned* a, unsigned b0, unsigned b1) {
    asm("mma.sync.aligned.m16n8k16.row.col.f32.f16.f16.f32 "
        "{%0,%1,%2,%3}, {%4,%5,%6,%7}, {%8,%9}, {%0,%1,%2,%3};"
        : "+f"(c[0]), "+f"(c[1]), "+f"(c[2]), "+f"(c[3])
        : "r"(a[0]), "r"(a[1]), "r"(a[2]), "r"(a[3]), "r"(b0), "r"(b1));
}
__device__ __forceinline__ void ldsm4(unsigned* r, uint32_t addr) {
    asm volatile("ldmatrix.sync.aligned.m8n8.x4.shared.b16 {%0,%1,%2,%3}, [%4];"
        : "=r"(r[0]), "=r"(r[1]), "=r"(r[2]), "=r"(r[3]) : "r"(addr));
}
__device__ __forceinline__ uint32_t smem_u32(const void* p) {
    uint32_t a;
    asm("{ .reg .u64 t; cvta.to.shared.u64 t, %1; cvt.u32.u64 %0, t; }" : "=r"(a) : "l"(p));
    return a;
}
__device__ __forceinline__ void cpa16(uint32_t dst, const void* src) {
    asm volatile("cp.async.cg.shared.global [%0], [%1], 16;" :: "r"(dst), "l"(src) : "memory");
}

// ---------------------------------------------------------------------------
// fp16-split GEMM: CTA tile 128x256, 16 warps at 32x64 (512 threads),
// k-chunk 32, 3-stage cp.async pipeline, ldmatrix loads. Split mmas issued
// in term sweeps (hh*16, hl*16, lh*16) for dependency distance 16.
// ---------------------------------------------------------------------------
#define STAGE_B 61440u    // Ahi 10240 | Alo 10240 | Whi 20480 | Wlo 20480
struct G5 { const __half* Ah; const __half* Al; int wbase; int wadd;
            const float* bias; float* C; __half* Chi; __half* Clo;
            int chunk; int split; };
struct G5Args { G5 s[6]; };

__global__ __launch_bounds__(512) void gemm_tc(G5Args ga)
{
    extern __shared__ __half smh[];
    const uint32_t sm32 = smem_u32(smh);
    const int tid = threadIdx.x, lane = tid & 31, wid = tid >> 5;
    const int wm = wid & 3, wn = wid >> 2;
    const int qr = lane >> 2, qc = lane & 3;
    const uint32_t ro = (lane & 7) + ((lane >> 3) & 1) * 8;
    const uint32_t co = (lane >> 4) * 8;

    const G5 sl = ga.s[blockIdx.z];
    const int m0 = blockIdx.y * 128, n0 = blockIdx.x * 256;
    const int widx = sl.chunk ? (1 + (m0 % 384) / 128) : sl.wadd;
    const __half* Wh = g_wh + (size_t)(sl.wbase + widx) * WKN;
    const __half* Wl = g_wl + (size_t)(sl.wbase + widx) * WKN;
    const float*  bp = sl.bias ? sl.bias + widx * 512 : nullptr;
    const int split = sl.split;

    auto issue = [&](int c) {
        const uint32_t base = sm32 + (uint32_t)(c % 3) * STAGE_B;
        const int kb = c * 32;
        {
            int row = tid >> 2, seg = tid & 3;
            uint32_t d = base + row * 80 + seg * 16;
            size_t gA = (size_t)(m0 + row) * 512 + kb + seg * 8;
            cpa16(d, sl.Ah + gA);
            if (split) cpa16(d + 10240, sl.Al + gA);
        }
#pragma unroll
        for (int r = 0; r < 2; r++) {
            int e = tid + r * 512;
            int row = e >> 2, seg = e & 3;
            uint32_t d = base + 20480 + row * 80 + seg * 16;
            size_t gW = (size_t)(n0 + row) * 512 + kb + seg * 8;
            cpa16(d, Wh + gW);
            if (split) cpa16(d + 20480, Wl + gW);
        }
    };

    float acc[2][8][4];
#pragma unroll
    for (int mi = 0; mi < 2; mi++)
#pragma unroll
        for (int ni = 0; ni < 8; ni++)
#pragma unroll
            for (int j = 0; j < 4; j++) acc[mi][ni][j] = 0.f;

    issue(0);
    asm volatile("cp.async.commit_group;" ::: "memory");
    issue(1);
    asm volatile("cp.async.commit_group;" ::: "memory");

    for (int c = 0; c < 16; c++) {
        asm volatile("cp.async.wait_group 1;" ::: "memory");
        __syncthreads();
        const uint32_t sA = sm32 + (uint32_t)(c % 3) * STAGE_B;
        const uint32_t sW = sA + 20480;
#pragma unroll
        for (int ks = 0; ks < 2; ks++) {
            unsigned ah[2][4], al[2][4], wh4[4][4], wl4[4][4];
#pragma unroll
            for (int mi = 0; mi < 2; mi++) {
                uint32_t ra = sA + ((wm*32 + mi*16 + ro) * 40 + ks*16 + co) * 2;
                ldsm4(ah[mi], ra);
                if (split) ldsm4(al[mi], ra + 10240);
            }
#pragma unroll
            for (int p = 0; p < 4; p++) {
                uint32_t rw = sW + ((wn*64 + p*16 + ro) * 40 + ks*16 + co) * 2;
                ldsm4(wh4[p], rw);
                if (split) ldsm4(wl4[p], rw + 20480);
            }
            // term sweep 1: Ah x Wh (16 independent accs)
#pragma unroll
            for (int p = 0; p < 4; p++)
#pragma unroll
                for (int mi = 0; mi < 2; mi++) {
                    mma_f16(acc[mi][2*p],   ah[mi], wh4[p][0], wh4[p][2]);
                    mma_f16(acc[mi][2*p+1], ah[mi], wh4[p][1], wh4[p][3]);
                }
            if (split) {
                // term sweep 2: Ah x Wl
#pragma unroll
                for (int p = 0; p < 4; p++)
#pragma unroll
                    for (int mi = 0; mi < 2; mi++) {
                        mma_f16(acc[mi][2*p],   ah[mi], wl4[p][0], wl4[p][2]);
                        mma_f16(acc[mi][2*p+1], ah[mi], wl4[p][1], wl4[p][3]);
                    }
                // term sweep 3: Al x Wh
#pragma unroll
                for (int p = 0; p < 4; p++)
#pragma unroll
                    for (int mi = 0; mi < 2; mi++) {
                        mma_f16(acc[mi][2*p],   al[mi], wh4[p][0], wh4[p][2]);
                        mma_f16(acc[mi][2*p+1], al[mi], wh4[p][1], wh4[p][3]);
                    }
            }
        }
        if (c + 2 < 16) issue(c + 2);
        asm volatile("cp.async.commit_group;" ::: "memory");
    }

    // epilogue
#pragma unroll
    for (int mi = 0; mi < 2; mi++) {
#pragma unroll
        for (int ni = 0; ni < 8; ni++) {
            int row = m0 + wm * 32 + mi * 16 + qr;
            int col = n0 + wn * 64 + ni * 8 + 2 * qc;
            float bx = 0.f, by = 0.f;
            if (bp) { float2 bb = *(const float2*)(bp + col); bx = bb.x; by = bb.y; }
            float v00 = acc[mi][ni][0] + bx, v01 = acc[mi][ni][1] + by;
            float v10 = acc[mi][ni][2] + bx, v11 = acc[mi][ni][3] + by;
            if (sl.Chi) {
                __half h0,h1,l0,l1;
                split_h(v00,h0,l0); split_h(v01,h1,l1);
                *(unsigned*)(sl.Chi + (size_t)row*512 + col) = pack2(h0,h1);
                *(unsigned*)(sl.Clo + (size_t)row*512 + col) = pack2(l0,l1);
                split_h(v10,h0,l0); split_h(v11,h1,l1);
                *(unsigned*)(sl.Chi + (size_t)(row+8)*512 + col) = pack2(h0,h1);
                *(unsigned*)(sl.Clo + (size_t)(row+8)*512 + col) = pack2(l0,l1);
            } else {
                float2 o0 = { v00, v01 }, o1 = { v10, v11 };
                *(float2*)(sl.C + (size_t)row * 512 + col)       = o0;
                *(float2*)(sl.C + (size_t)(row + 8) * 512 + col) = o1;
            }
        }
    }
}

// ---------------------------------------------------------------------------
// split kernels: f32 -> (hi, lo) fp16 pairs
// ---------------------------------------------------------------------------
struct SpEnt { const float* src; __half* hi; __half* lo; int n; };
struct SpArgs { SpEnt e[5]; };

__global__ __launch_bounds__(256) void split_kernel(SpArgs sa)
{
    SpEnt E = sa.e[blockIdx.z];
    int stride = gridDim.x * 256;
    for (int i = blockIdx.x * 256 + threadIdx.x; i * 4 < E.n; i += stride) {
        float4 v = ((const float4*)E.src)[i];
        __half h0,h1,h2,h3,l0,l1,l2,l3;
        split_h(v.x,h0,l0); split_h(v.y,h1,l1); split_h(v.z,h2,l2); split_h(v.w,h3,l3);
        *(uint2*)(E.hi + 4*i) = make_uint2(pack2(h0,h1), pack2(h2,h3));
        *(uint2*)(E.lo + 4*i) = make_uint2(pack2(l0,l1), pack2(l2,l3));
    }
}

__global__ __launch_bounds__(256) void diff_split_kernel(
    const float4* __restrict__ t1, const float4* __restrict__ t2,
    __half* __restrict__ hi, __half* __restrict__ lo)
{
    int i = blockIdx.x * 256 + threadIdx.x;
    float4 a = t1[i], b = t2[i];
    __half h0,h1,h2,h3,l0,l1,l2,l3;
    split_h(a.x-b.x,h0,l0); split_h(a.y-b.y,h1,l1);
    split_h(a.z-b.z,h2,l2); split_h(a.w-b.w,h3,l3);
    *(uint2*)(hi + 4*i) = make_uint2(pack2(h0,h1), pack2(h2,h3));
    *(uint2*)(lo + 4*i) = make_uint2(pack2(l0,l1), pack2(l2,l3));
}

// ---------------------------------------------------------------------------
// Single-pass fp16-split attention (R10 structure) with term-sweep mma
// scheduling. T = MI*128; warp w owns s-slice [w*MI*16, (w+1)*MI*16).
// ---------------------------------------------------------------------------
template<int MI>
__global__ __launch_bounds__(256) void attn_tc(
    const __half* __restrict__ Qbh, const __half* __restrict__ Qbl,
    const __half* __restrict__ Kbh, const __half* __restrict__ Kbl,
    const __half* __restrict__ Vbh, const __half* __restrict__ Vbl,
    const float* __restrict__ temp,
    const float* __restrict__ addend, float* __restrict__ Ob,
    int tempBase)
{
    const int T = MI * 128;
    const int QS = T + 8;
    extern __shared__ __half smh[];
    __half* Khi = smh;                       // [T][40]
    __half* Klo = Khi + T * 40;
    __half* Vhi = Klo + T * 40;
    __half* Vlo = Vhi + T * 40;
    __half* Qhi = Vlo + T * 40;              // [32][QS]
    __half* Qlo = Qhi + 32 * QS;
    float*  redM = (float*)(Qlo + 32 * QS);  // [2][128]
    float*  redS = redM + 256;               // [2][128]

    const uint32_t smA   = smem_u32(smh);
    const uint32_t KVoff = (uint32_t)T * 80;
    const uint32_t Qoff  = (uint32_t)32 * QS * 2;

    const int h = blockIdx.x, c = blockIdx.y, b = blockIdx.z;
    const int tid = threadIdx.x, lane = tid & 31, wid = tid >> 5;
    const int qr = lane >> 2, qc = lane & 3;
    const uint32_t ro = (lane & 7) + ((lane >> 3) & 1) * 8;
    const uint32_t co = (lane >> 4) * 8;
    const size_t off = (size_t)b * (T_*D_) + (size_t)c * (128*D_) + (size_t)h * 32 * T;
    const float scale = temp[(tempBase + c) * H_ + h];

    for (int idx = tid; idx < 32 * T; idx += 256) {
        int i = idx / T, t = idx - i * T;
        Khi[t*40 + i] = Kbh[off + idx];
        Klo[t*40 + i] = Kbl[off + idx];
        Vhi[t*40 + i] = Vbh[off + idx];
        Vlo[t*40 + i] = Vbl[off + idx];
        Qhi[i*QS + t] = Qbh[off + idx];
        Qlo[i*QS + t] = Qbl[off + idx];
    }
    __syncthreads();

    const uint32_t KhiA = smA;
    const uint32_t VhiA = smA + 2 * KVoff;
    const uint32_t QhiA = smA + 4 * KVoff;

    const int s0 = wid * MI * 16;

    // V A-fragments held for the whole kernel
    unsigned vh[MI][2][4], vl[MI][2][4];
#pragma unroll
    for (int mi = 0; mi < MI; mi++)
#pragma unroll
        for (int ks = 0; ks < 2; ks++) {
            uint32_t rv = VhiA + (((uint32_t)(s0 + mi*16) + ro) * 40 + ks*16 + co) * 2;
            ldsm4(vh[mi][ks], rv);
            ldsm4(vl[mi][ks], rv + KVoff);
        }

    float o[MI][4][4];
#pragma unroll
    for (int mi = 0; mi < MI; mi++)
#pragma unroll
        for (int ni = 0; ni < 4; ni++)
#pragma unroll
            for (int j = 0; j < 4; j++) o[mi][ni][j] = 0.f;

    for (int tb = 0; tb < T/16; tb++) {
        const int t0 = tb * 16;
        const int buf = (tb & 1) * 128;

        unsigned kh[2][4], kl[2][4];
#pragma unroll
        for (int ks = 0; ks < 2; ks++) {
            uint32_t rk = KhiA + (((uint32_t)t0 + ro) * 40 + ks*16 + co) * 2;
            ldsm4(kh[ks], rk);
            ldsm4(kl[ks], rk + KVoff);
        }

        // S^T = V^T K, 3-term sweeps (distance 2*MI per acc)
        float acc[MI][2][4];
#pragma unroll
        for (int mi = 0; mi < MI; mi++)
#pragma unroll
            for (int nt = 0; nt < 2; nt++)
#pragma unroll
                for (int j = 0; j < 4; j++) acc[mi][nt][j] = 0.f;
#pragma unroll
        for (int ks = 0; ks < 2; ks++)
#pragma unroll
            for (int mi = 0; mi < MI; mi++) {
                mma_f16(acc[mi][0], vh[mi][ks], kh[ks][0], kh[ks][2]);
                mma_f16(acc[mi][1], vh[mi][ks], kh[ks][1], kh[ks][3]);
            }
#pragma unroll
        for (int ks = 0; ks < 2; ks++)
#pragma unroll
            for (int mi = 0; mi < MI; mi++) {
                mma_f16(acc[mi][0], vh[mi][ks], kl[ks][0], kl[ks][2]);
                mma_f16(acc[mi][1], vh[mi][ks], kl[ks][1], kl[ks][3]);
            }
#pragma unroll
        for (int ks = 0; ks < 2; ks++)
#pragma unroll
            for (int mi = 0; mi < MI; mi++) {
                mma_f16(acc[mi][0], vl[mi][ks], kh[ks][0], kh[ks][2]);
                mma_f16(acc[mi][1], vl[mi][ks], kh[ks][1], kh[ks][3]);
            }
#pragma unroll
        for (int mi = 0; mi < MI; mi++)
#pragma unroll
            for (int nt = 0; nt < 2; nt++)
#pragma unroll
                for (int j = 0; j < 4; j++) acc[mi][nt][j] *= scale;

        // warp-level max
        float mx[2][2];
#pragma unroll
        for (int nt = 0; nt < 2; nt++) {
            mx[nt][0] = -3.0e38f; mx[nt][1] = -3.0e38f;
#pragma unroll
            for (int mi = 0; mi < MI; mi++) {
                mx[nt][0] = fmaxf(mx[nt][0], fmaxf(acc[mi][nt][0], acc[mi][nt][2]));
                mx[nt][1] = fmaxf(mx[nt][1], fmaxf(acc[mi][nt][1], acc[mi][nt][3]));
            }
#pragma unroll
            for (int d = 4; d < 32; d <<= 1) {
                mx[nt][0] = fmaxf(mx[nt][0], __shfl_xor_sync(0xffffffffu, mx[nt][0], d));
                mx[nt][1] = fmaxf(mx[nt][1], __shfl_xor_sync(0xffffffffu, mx[nt][1], d));
            }
        }
        if (lane < 4) {
#pragma unroll
            for (int nt = 0; nt < 2; nt++) {
                redM[buf + wid*16 + nt*8 + 2*lane]     = mx[nt][0];
                redM[buf + wid*16 + nt*8 + 2*lane + 1] = mx[nt][1];
            }
        }
        __syncthreads();

        float gm[2][2];
#pragma unroll
        for (int nt = 0; nt < 2; nt++)
#pragma unroll
            for (int j = 0; j < 2; j++) {
                int t = nt*8 + 2*qc + j;
                float g = -3.0e38f;
#pragma unroll
                for (int ww = 0; ww < 8; ww++)
                    g = fmaxf(g, redM[buf + ww*16 + t]);
                gm[nt][j] = g;
            }

        float sm[2][2] = {{0.f,0.f},{0.f,0.f}};
#pragma unroll
        for (int mi = 0; mi < MI; mi++)
#pragma unroll
            for (int nt = 0; nt < 2; nt++) {
                acc[mi][nt][0] = __expf(acc[mi][nt][0] - gm[nt][0]);
                acc[mi][nt][1] = __expf(acc[mi][nt][1] - gm[nt][1]);
                acc[mi][nt][2] = __expf(acc[mi][nt][2] - gm[nt][0]);
                acc[mi][nt][3] = __expf(acc[mi][nt][3] - gm[nt][1]);
                sm[nt][0] += acc[mi][nt][0] + acc[mi][nt][2];
                sm[nt][1] += acc[mi][nt][1] + acc[mi][nt][3];
            }
#pragma unroll
        for (int nt = 0; nt < 2; nt++)
#pragma unroll
            for (int d = 4; d < 32; d <<= 1) {
                sm[nt][0] += __shfl_xor_sync(0xffffffffu, sm[nt][0], d);
                sm[nt][1] += __shfl_xor_sync(0xffffffffu, sm[nt][1], d);
            }
        if (lane < 4) {
#pragma unroll
            for (int nt = 0; nt < 2; nt++) {
                redS[buf + wid*16 + nt*8 + 2*lane]     = sm[nt][0];
                redS[buf + wid*16 + nt*8 + 2*lane + 1] = sm[nt][1];
            }
        }
        __syncthreads();

        float li[2][2];
#pragma unroll
        for (int nt = 0; nt < 2; nt++)
#pragma unroll
            for (int j = 0; j < 2; j++) {
                int t = nt*8 + 2*qc + j;
                float s = 0.f;
#pragma unroll
                for (int ww = 0; ww < 8; ww++)
                    s += redS[buf + ww*16 + t];
                li[nt][j] = 1.f / s;
            }

        unsigned qh4[2][4], ql4[2][4];
#pragma unroll
        for (int p2 = 0; p2 < 2; p2++) {
            uint32_t rq = QhiA + ((p2*16 + ro) * (uint32_t)QS + (uint32_t)t0 + co) * 2;
            ldsm4(qh4[p2], rq);
            ldsm4(ql4[p2], rq + Qoff);
        }

        // P normalize + split (all mi first), then term-sweep O mmas
        unsigned phA[MI][4], plA[MI][4];
#pragma unroll
        for (int mi = 0; mi < MI; mi++) {
            float p00 = acc[mi][0][0]*li[0][0], p01 = acc[mi][0][1]*li[0][1];
            float p02 = acc[mi][0][2]*li[0][0], p03 = acc[mi][0][3]*li[0][1];
            float p10 = acc[mi][1][0]*li[1][0], p11 = acc[mi][1][1]*li[1][1];
            float p12 = acc[mi][1][2]*li[1][0], p13 = acc[mi][1][3]*li[1][1];
            __half h00,l00,h01,l01,h02,l02,h03,l03;
            split_h(p00,h00,l00); split_h(p01,h01,l01);
            split_h(p02,h02,l02); split_h(p03,h03,l03);
            phA[mi][0] = pack2(h00,h01); phA[mi][1] = pack2(h02,h03);
            plA[mi][0] = pack2(l00,l01); plA[mi][1] = pack2(l02,l03);
            split_h(p10,h00,l00); split_h(p11,h01,l01);
            split_h(p12,h02,l02); split_h(p13,h03,l03);
            phA[mi][2] = pack2(h00,h01); phA[mi][3] = pack2(h02,h03);
            plA[mi][2] = pack2(l00,l01); plA[mi][3] = pack2(l02,l03);
        }
#pragma unroll
        for (int p2 = 0; p2 < 2; p2++)
#pragma unroll
            for (int mi = 0; mi < MI; mi++) {
                mma_f16(o[mi][2*p2],   phA[mi], qh4[p2][0], qh4[p2][2]);
                mma_f16(o[mi][2*p2+1], phA[mi], qh4[p2][1], qh4[p2][3]);
            }
#pragma unroll
        for (int p2 = 0; p2 < 2; p2++)
#pragma unroll
            for (int mi = 0; mi < MI; mi++) {
                mma_f16(o[mi][2*p2],   phA[mi], ql4[p2][0], ql4[p2][2]);
                mma_f16(o[mi][2*p2+1], phA[mi], ql4[p2][1], ql4[p2][3]);
            }
#pragma unroll
        for (int p2 = 0; p2 < 2; p2++)
#pragma unroll
            for (int mi = 0; mi < MI; mi++) {
                mma_f16(o[mi][2*p2],   plA[mi], qh4[p2][0], qh4[p2][2]);
                mma_f16(o[mi][2*p2+1], plA[mi], qh4[p2][1], qh4[p2][3]);
            }
    }

    // epilogue: Out^T[s][i] (+ addend)
#pragma unroll
    for (int mi = 0; mi < MI; mi++)
#pragma unroll
        for (int ni = 0; ni < 4; ni++) {
            int icol = ni * 8 + 2 * qc;
            int srow = s0 + mi * 16 + qr;
            size_t base = off + (size_t)icol * T + srow;
            if (addend != nullptr) {
                Ob[base]         = o[mi][ni][0] + addend[base];
                Ob[base + T]     = o[mi][ni][1] + addend[base + T];
                Ob[base + 8]     = o[mi][ni][2] + addend[base + 8];
                Ob[base + T + 8] = o[mi][ni][3] + addend[base + T + 8];
            } else {
                Ob[base]         = o[mi][ni][0];
                Ob[base + T]     = o[mi][ni][1];
                Ob[base + 8]     = o[mi][ni][2];
                Ob[base + T + 8] = o[mi][ni][3];
            }
        }
}

// ---------------------------------------------------------------------------
// LayerNorm: one warp per 512-wide row; emits split fp16 directly.
// ---------------------------------------------------------------------------
__global__ __launch_bounds__(256) void ln_kernel(
    const float* __restrict__ X, const float* __restrict__ gw,
    const float* __restrict__ gb, __half* __restrict__ Yh, __half* __restrict__ Yl)
{
    const int row  = blockIdx.x * 8 + (threadIdx.x >> 5);
    const int lane = threadIdx.x & 31;
    const float4* xr = (const float4*)(X + (size_t)row * D_);
    float4 v[4];
    float s = 0.f, ss = 0.f;
#pragma unroll
    for (int w = 0; w < 4; w++) {
        v[w] = xr[w*32 + lane];
        s  += v[w].x + v[w].y + v[w].z + v[w].w;
        ss += v[w].x*v[w].x + v[w].y*v[w].y + v[w].z*v[w].z + v[w].w*v[w].w;
    }
#pragma unroll
    for (int o = 16; o > 0; o >>= 1) {
        s  += __shfl_xor_sync(0xffffffffu, s, o);
        ss += __shfl_xor_sync(0xffffffffu, ss, o);
    }
    const float mean = s * (1.f/512.f);
    const float var  = ss * (1.f/512.f) - mean*mean;
    const float r = rsqrtf(var + 1e-5f);
    const float4* gr = (const float4*)gw;
    const float4* br = (const float4*)gb;
#pragma unroll
    for (int w = 0; w < 4; w++) {
        float4 gv = gr[w*32 + lane];
        float4 bv = br[w*32 + lane];
        float o0 = (v[w].x - mean) * r * gv.x + bv.x;
        float o1 = (v[w].y - mean) * r * gv.y + bv.y;
        float o2 = (v[w].z - mean) * r * gv.z + bv.z;
        float o3 = (v[w].w - mean) * r * gv.w + bv.w;
        __half h0,h1,h2,h3,l0,l1,l2,l3;
        split_h(o0,h0,l0); split_h(o1,h1,l1); split_h(o2,h2,l2); split_h(o3,h3,l3);
        size_t idx = (size_t)row * D_ + (w*32 + lane) * 4;
        *(uint2*)(Yh + idx) = make_uint2(pack2(h0,h1), pack2(h2,h3));
        *(uint2*)(Yl + idx) = make_uint2(pack2(l0,l1), pack2(l2,l3));
    }
}

// ---------------------------------------------------------------------------
// Combine: out = t1*sig(ld) + t2*(1-sig(ld)), ld = (t1-t2)@fw^T (bias cancels)
// ---------------------------------------------------------------------------
__global__ __launch_bounds__(256) void fuse2_kernel(
    const float4* __restrict__ t1, const float4* __restrict__ t2,
    const float4* __restrict__ ld, float4* __restrict__ out)
{
    int i = blockIdx.x * 256 + threadIdx.x;
    float4 x1 = t1[i], x2 = t2[i], d = ld[i];
    float a0 = 1.f / (1.f + __expf(-d.x));
    float a1 = 1.f / (1.f + __expf(-d.y));
    float a2 = 1.f / (1.f + __expf(-d.z));
    float a3 = 1.f / (1.f + __expf(-d.w));
    float4 o;
    o.x = x1.x * a0 + x2.x * (1.f - a0);
    o.y = x1.y * a1 + x2.y * (1.f - a1);
    o.z = x1.z * a2 + x2.z * (1.f - a2);
    o.w = x1.w * a3 + x2.w * (1.f - a3);
    out[i] = o;
}

// ---------------------------------------------------------------------------
extern "C" void kernel_launch(void* const* d_in, const int* in_sizes, int n_in,
                              void* d_out, int out_size)
{
    (void)in_sizes; (void)n_in; (void)out_size;
    const float* x    = (const float*)d_in[0];
    const float* qw   = (const float*)d_in[1];
    const float* qb   = (const float*)d_in[2];
    const float* kw   = (const float*)d_in[3];
    const float* kb   = (const float*)d_in[4];
    const float* vw   = (const float*)d_in[5];
    const float* vb   = (const float*)d_in[6];
    const float* temp = (const float*)d_in[7];
    const float* lng  = (const float*)d_in[8];
    const float* lnb  = (const float*)d_in[9];
    const float* fw   = (const float*)d_in[10];
    (void)d_in[11];
    float* out = (float*)d_out;

    float *xr, *t1, *t2, *a1;
    __half *qh,*ql,*kh2,*kl2,*vh2,*vl2, *q2h,*q2l,*k2h,*k2l,*v2h,*v2l;
    __half *xh, *xl, *lnh, *lnl, *dh, *dl, *wh, *wl;
    cudaGetSymbolAddress((void**)&xr, g_xr);
    cudaGetSymbolAddress((void**)&t1, g_t1);
    cudaGetSymbolAddress((void**)&t2, g_t2);
    cudaGetSymbolAddress((void**)&a1, g_a1);
    cudaGetSymbolAddress((void**)&qh, g_qh);   cudaGetSymbolAddress((void**)&ql, g_ql);
    cudaGetSymbolAddress((void**)&kh2, g_kh);  cudaGetSymbolAddress((void**)&kl2, g_kl);
    cudaGetSymbolAddress((void**)&vh2, g_vh);  cudaGetSymbolAddress((void**)&vl2, g_vl);
    cudaGetSymbolAddress((void**)&q2h, g_q2h); cudaGetSymbolAddress((void**)&q2l, g_q2l);
    cudaGetSymbolAddress((void**)&k2h, g_k2h); cudaGetSymbolAddress((void**)&k2l, g_k2l);
    cudaGetSymbolAddress((void**)&v2h, g_v2h); cudaGetSymbolAddress((void**)&v2l, g_v2l);
    cudaGetSymbolAddress((void**)&xh, g_xh);   cudaGetSymbolAddress((void**)&xl, g_xl);
    cudaGetSymbolAddress((void**)&lnh, g_lnh); cudaGetSymbolAddress((void**)&lnl, g_lnl);
    cudaGetSymbolAddress((void**)&dh, g_dh);   cudaGetSymbolAddress((void**)&dl, g_dl);
    cudaGetSymbolAddress((void**)&wh, g_wh);   cudaGetSymbolAddress((void**)&wl, g_wl);

    const int gemmSmem = 3 * STAGE_B;                                 // 184320
    const int smem384 = (4*384*40 + 2*32*392) * 2 + 4*128*4;          // 175104
    const int smem128 = (4*128*40 + 2*32*136) * 2 + 4*128*4;          // 60416
    cudaFuncSetAttribute(gemm_tc, cudaFuncAttributeMaxDynamicSharedMemorySize, gemmSmem);
    cudaFuncSetAttribute(attn_tc<3>, cudaFuncAttributeMaxDynamicSharedMemorySize, smem384);
    cudaFuncSetAttribute(attn_tc<1>, cudaFuncAttributeMaxDynamicSharedMemorySize, smem128);

    // 1) pre-split x and all weight matrices
    SpArgs sp1;
    sp1.e[0] = { x,  xh,          xl,          BTD    };
    sp1.e[1] = { qw, wh + 0,      wl + 0,      5*WKN  };
    sp1.e[2] = { kw, wh + (size_t)5*WKN,  wl + (size_t)5*WKN,  5*WKN  };
    sp1.e[3] = { vw, wh + (size_t)10*WKN, wl + (size_t)10*WKN, 5*WKN  };
    sp1.e[4] = { fw, wh + (size_t)15*WKN, wl + (size_t)15*WKN, WKN    };
    split_kernel<<<dim3(512, 1, 5), 256>>>(sp1);

    // 2) QKV GEMMs (all split)
    G5Args ga1;
    ga1.s[0] = { xh, xl, 0,  0, qb, nullptr, qh,  ql,  0, 1 };
    ga1.s[1] = { xh, xl, 5,  0, kb, nullptr, kh2, kl2, 0, 1 };
    ga1.s[2] = { xh, xl, 10, 0, vb, nullptr, vh2, vl2, 0, 1 };
    ga1.s[3] = { xh, xl, 0,  0, qb, nullptr, q2h, q2l, 1, 1 };
    ga1.s[4] = { xh, xl, 5,  0, kb, nullptr, k2h, k2l, 1, 1 };
    ga1.s[5] = { xh, xl, 10, 0, vb, nullptr, v2h, v2l, 1, 1 };
    gemm_tc<<<dim3(2, 96, 6), 512, gemmSmem>>>(ga1);

    attn_tc<3><<<dim3(H_, 1, B_), 256, smem384>>>(qh, ql, kh2, kl2, vh2, vl2, temp, nullptr, xr, 0);
    attn_tc<1><<<dim3(H_, 3, B_), 256, smem128>>>(q2h, q2l, k2h, k2l, v2h, v2l, temp, xr, t1, 1);

    // 3) LayerNorm(t1) -> split fp16
    ln_kernel<<<M_/8, 256>>>(t1, lng, lnb, lnh, lnl);

    // 4) block4 QKV on LN output
    G5Args ga2;
    ga2.s[0] = { lnh, lnl, 0,  4, qb, nullptr, qh,  ql,  0, 1 };
    ga2.s[1] = { lnh, lnl, 5,  4, kb, nullptr, kh2, kl2, 0, 1 };
    ga2.s[2] = { lnh, lnl, 10, 4, vb, nullptr, vh2, vl2, 0, 1 };
    ga2.s[3] = ga2.s[0]; ga2.s[4] = ga2.s[0]; ga2.s[5] = ga2.s[0];
    gemm_tc<<<dim3(2, 96, 3), 512, gemmSmem>>>(ga2);

    attn_tc<3><<<dim3(H_, 1, B_), 256, smem384>>>(qh, ql, kh2, kl2, vh2, vl2, temp, xr, t2, 4);

    // 5) fusion: single GEMM on the difference (bias cancels in softmax)
    diff_split_kernel<<<BTD/4/256, 256>>>((const float4*)t1, (const float4*)t2, dh, dl);
    G5Args ga3;
    ga3.s[0] = { dh, dl, 15, 0, nullptr, a1, nullptr, nullptr, 0, 0 };
    ga3.s[1] = ga3.s[0]; ga3.s[2] = ga3.s[0]; ga3.s[3] = ga3.s[0];
    ga3.s[4] = ga3.s[0]; ga3.s[5] = ga3.s[0];
    gemm_tc<<<dim3(2, 96, 1), 512, gemmSmem>>>(ga3);

    fuse2_kernel<<<BTD/4/256, 256>>>((const float4*)t1, (const float4*)t2,
                                     (const float4*)a1, (float4*)out);
}

// round 12
// speedup vs baseline: 1.6230x; 1.6230x over previous
#include <cuda_runtime.h>
#include <cuda_fp16.h>
#include <math.h>
#include <stdint.h>

#define B_  32
#define T_  384
#define D_  512
#define H_  16
#define BTD (B_*T_*D_)     // 6291456
#define M_  (B_*T_)        // 12288
#define WKN (512*512)

// ---------------- scratch (static device globals; no cudaMalloc) ----------
__device__ float g_xr[BTD], g_t1[BTD], g_t2[BTD], g_a1[BTD];
__device__ __half g_qh[BTD], g_ql[BTD], g_kh[BTD], g_kl[BTD], g_vh[BTD], g_vl[BTD];
__device__ __half g_q2h[BTD], g_q2l[BTD], g_k2h[BTD], g_k2l[BTD], g_v2h[BTD], g_v2l[BTD];
__device__ __half g_xh[BTD],  g_xl[BTD];
__device__ __half g_lnh[BTD], g_lnl[BTD];
__device__ __half g_dh[BTD],  g_dl[BTD];
__device__ __half g_wh[16*WKN], g_wl[16*WKN];   // [qw0-4 | kw0-4 | vw0-4 | fw]

// ---------------- helpers --------------------------------------------------
__device__ __forceinline__ void split_h(float x, __half& hi, __half& lo) {
    hi = __float2half_rn(x);
    lo = __float2half_rn(x - __half2float(hi));
}
__device__ __forceinline__ unsigned pack2(__half a, __half b) {
    __half2 h = __halves2half2(a, b);
    return *reinterpret_cast<unsigned*>(&h);
}
__device__ __forceinline__ void mma_f16(float* c, const unsigned* a, unsigned b0, unsigned b1) {
    asm volatile("mma.sync.aligned.m16n8k16.row.col.f32.f16.f16.f32 "
        "{%0,%1,%2,%3}, {%4,%5,%6,%7}, {%8,%9}, {%0,%1,%2,%3};"
        : "+f"(c[0]), "+f"(c[1]), "+f"(c[2]), "+f"(c[3])
        : "r"(a[0]), "r"(a[1]), "r"(a[2]), "r"(a[3]), "r"(b0), "r"(b1));
}
__device__ __forceinline__ void ldsm4(unsigned* r, uint32_t addr) {
    asm volatile("ldmatrix.sync.aligned.m8n8.x4.shared.b16 {%0,%1,%2,%3}, [%4];"
        : "=r"(r[0]), "=r"(r[1]), "=r"(r[2]), "=r"(r[3]) : "r"(addr));
}
__device__ __forceinline__ uint32_t smem_u32(const void* p) {
    uint32_t a;
    asm("{ .reg .u64 t; cvta.to.shared.u64 t, %1; cvt.u32.u64 %0, t; }" : "=r"(a) : "l"(p));
    return a;
}
__device__ __forceinline__ void cpa16(uint32_t dst, const void* src) {
    asm volatile("cp.async.cg.shared.global [%0], [%1], 16;" :: "r"(dst), "l"(src) : "memory");
}

// ---------------------------------------------------------------------------
// fp16-split GEMM: CTA tile 128x256, 16 warps at 32x64 each (512 threads),
// k-chunk 32, 3-stage cp.async pipeline, ldmatrix operand loads.
// split=1: 3-mma hi/lo; split=0: single fp16 (hi inputs only).
// ---------------------------------------------------------------------------
#define STAGE_B 61440u    // Ahi 10240 | Alo 10240 | Whi 20480 | Wlo 20480
struct G5 { const __half* Ah; const __half* Al; int wbase; int wadd;
            const float* bias; float* C; __half* Chi; __half* Clo;
            int chunk; int split; };
struct G5Args { G5 s[6]; };

__global__ __launch_bounds__(512) void gemm_tc(G5Args ga)
{
    extern __shared__ __half smh[];
    const uint32_t sm32 = smem_u32(smh);
    const int tid = threadIdx.x, lane = tid & 31, wid = tid >> 5;
    const int wm = wid & 3, wn = wid >> 2;
    const int qr = lane >> 2, qc = lane & 3;
    const uint32_t ro = (lane & 7) + ((lane >> 3) & 1) * 8;
    const uint32_t co = (lane >> 4) * 8;

    const G5 sl = ga.s[blockIdx.z];
    const int m0 = blockIdx.y * 128, n0 = blockIdx.x * 256;
    const int widx = sl.chunk ? (1 + (m0 % 384) / 128) : sl.wadd;
    const __half* Wh = g_wh + (size_t)(sl.wbase + widx) * WKN;
    const __half* Wl = g_wl + (size_t)(sl.wbase + widx) * WKN;
    const float*  bp = sl.bias ? sl.bias + widx * 512 : nullptr;
    const int split = sl.split;

    auto issue = [&](int c) {
        const uint32_t base = sm32 + (uint32_t)(c % 3) * STAGE_B;
        const int kb = c * 32;
        {
            int row = tid >> 2, seg = tid & 3;
            uint32_t d = base + row * 80 + seg * 16;
            size_t gA = (size_t)(m0 + row) * 512 + kb + seg * 8;
            cpa16(d, sl.Ah + gA);
            if (split) cpa16(d + 10240, sl.Al + gA);
        }
#pragma unroll
        for (int r = 0; r < 2; r++) {
            int e = tid + r * 512;
            int row = e >> 2, seg = e & 3;
            uint32_t d = base + 20480 + row * 80 + seg * 16;
            size_t gW = (size_t)(n0 + row) * 512 + kb + seg * 8;
            cpa16(d, Wh + gW);
            if (split) cpa16(d + 20480, Wl + gW);
        }
    };

    float acc[2][8][4];
#pragma unroll
    for (int mi = 0; mi < 2; mi++)
#pragma unroll
        for (int ni = 0; ni < 8; ni++)
#pragma unroll
            for (int j = 0; j < 4; j++) acc[mi][ni][j] = 0.f;

    issue(0);
    asm volatile("cp.async.commit_group;" ::: "memory");
    issue(1);
    asm volatile("cp.async.commit_group;" ::: "memory");

    for (int c = 0; c < 16; c++) {
        asm volatile("cp.async.wait_group 1;" ::: "memory");
        __syncthreads();
        const uint32_t sA = sm32 + (uint32_t)(c % 3) * STAGE_B;
        const uint32_t sW = sA + 20480;
#pragma unroll
        for (int ks = 0; ks < 2; ks++) {
            unsigned ah[2][4], al[2][4];
#pragma unroll
            for (int mi = 0; mi < 2; mi++) {
                uint32_t ra = sA + ((wm*32 + mi*16 + ro) * 40 + ks*16 + co) * 2;
                ldsm4(ah[mi], ra);
                if (split) ldsm4(al[mi], ra + 10240);
            }
#pragma unroll
            for (int p = 0; p < 4; p++) {
                uint32_t rw = sW + ((wn*64 + p*16 + ro) * 40 + ks*16 + co) * 2;
                unsigned wh4[4], wl4[4];
                ldsm4(wh4, rw);
                if (split) ldsm4(wl4, rw + 20480);
#pragma unroll
                for (int mi = 0; mi < 2; mi++) {
                    mma_f16(acc[mi][2*p],   ah[mi], wh4[0], wh4[2]);
                    mma_f16(acc[mi][2*p+1], ah[mi], wh4[1], wh4[3]);
                    if (split) {
                        mma_f16(acc[mi][2*p],   ah[mi], wl4[0], wl4[2]);
                        mma_f16(acc[mi][2*p],   al[mi], wh4[0], wh4[2]);
                        mma_f16(acc[mi][2*p+1], ah[mi], wl4[1], wl4[3]);
                        mma_f16(acc[mi][2*p+1], al[mi], wh4[1], wh4[3]);
                    }
                }
            }
        }
        if (c + 2 < 16) issue(c + 2);
        asm volatile("cp.async.commit_group;" ::: "memory");
    }

    // epilogue
#pragma unroll
    for (int mi = 0; mi < 2; mi++) {
#pragma unroll
        for (int ni = 0; ni < 8; ni++) {
            int row = m0 + wm * 32 + mi * 16 + qr;
            int col = n0 + wn * 64 + ni * 8 + 2 * qc;
            float bx = 0.f, by = 0.f;
            if (bp) { float2 bb = *(const float2*)(bp + col); bx = bb.x; by = bb.y; }
            float v00 = acc[mi][ni][0] + bx, v01 = acc[mi][ni][1] + by;
            float v10 = acc[mi][ni][2] + bx, v11 = acc[mi][ni][3] + by;
            if (sl.Chi) {
                __half h0,h1,l0,l1;
                split_h(v00,h0,l0); split_h(v01,h1,l1);
                *(unsigned*)(sl.Chi + (size_t)row*512 + col) = pack2(h0,h1);
                *(unsigned*)(sl.Clo + (size_t)row*512 + col) = pack2(l0,l1);
                split_h(v10,h0,l0); split_h(v11,h1,l1);
                *(unsigned*)(sl.Chi + (size_t)(row+8)*512 + col) = pack2(h0,h1);
                *(unsigned*)(sl.Clo + (size_t)(row+8)*512 + col) = pack2(l0,l1);
            } else {
                float2 o0 = { v00, v01 }, o1 = { v10, v11 };
                *(float2*)(sl.C + (size_t)row * 512 + col)       = o0;
                *(float2*)(sl.C + (size_t)(row + 8) * 512 + col) = o1;
            }
        }
    }
}

// ---------------------------------------------------------------------------
// split kernels: f32 -> (hi, lo) fp16 pairs
// ---------------------------------------------------------------------------
struct SpEnt { const float* src; __half* hi; __half* lo; int n; };
struct SpArgs { SpEnt e[5]; };

__global__ __launch_bounds__(256) void split_kernel(SpArgs sa)
{
    SpEnt E = sa.e[blockIdx.z];
    int stride = gridDim.x * 256;
    for (int i = blockIdx.x * 256 + threadIdx.x; i * 4 < E.n; i += stride) {
        float4 v = ((const float4*)E.src)[i];
        __half h0,h1,h2,h3,l0,l1,l2,l3;
        split_h(v.x,h0,l0); split_h(v.y,h1,l1); split_h(v.z,h2,l2); split_h(v.w,h3,l3);
        *(uint2*)(E.hi + 4*i) = make_uint2(pack2(h0,h1), pack2(h2,h3));
        *(uint2*)(E.lo + 4*i) = make_uint2(pack2(l0,l1), pack2(l2,l3));
    }
}

__global__ __launch_bounds__(256) void diff_split_kernel(
    const float4* __restrict__ t1, const float4* __restrict__ t2,
    __half* __restrict__ hi, __half* __restrict__ lo)
{
    int i = blockIdx.x * 256 + threadIdx.x;
    float4 a = t1[i], b = t2[i];
    __half h0,h1,h2,h3,l0,l1,l2,l3;
    split_h(a.x-b.x,h0,l0); split_h(a.y-b.y,h1,l1);
    split_h(a.z-b.z,h2,l2); split_h(a.w-b.w,h3,l3);
    *(uint2*)(hi + 4*i) = make_uint2(pack2(h0,h1), pack2(h2,h3));
    *(uint2*)(lo + 4*i) = make_uint2(pack2(l0,l1), pack2(l2,l3));
}

// ---------------------------------------------------------------------------
// Two-pass fp16-split attention with ldmatrix operand loads (R7 structure),
// templated on warp count NW. K/V tiles [T][40], Q [32][QS]. Pass loops
// stride by NW; P scratch is per-warp [16][24].
// ---------------------------------------------------------------------------
template<int NW>
__global__ void attn_tc(
    const __half* __restrict__ Qbh, const __half* __restrict__ Qbl,
    const __half* __restrict__ Kbh, const __half* __restrict__ Kbl,
    const __half* __restrict__ Vbh, const __half* __restrict__ Vbl,
    const float* __restrict__ temp,
    const float* __restrict__ addend, float* __restrict__ Ob,
    int T, int tempBase)
{
    extern __shared__ __half smh[];
    const int QS = T + 8;
    __half* Khi = smh;                       // [T][40]
    __half* Klo = Khi + T * 40;
    __half* Vhi = Klo + T * 40;
    __half* Vlo = Vhi + T * 40;
    __half* Qhi = Vlo + T * 40;              // [32][QS]
    __half* Qlo = Qhi + 32 * QS;
    float*  Mv  = (float*)(Qlo + 32 * QS);
    float*  Lv  = Mv + T;
    __half* Pshi = (__half*)(Lv + T);        // NW warps * [16][24]
    __half* Pslo = Pshi + NW * 16 * 24;

    const uint32_t smA   = smem_u32(smh);
    const uint32_t KVoff = (uint32_t)T * 80;
    const uint32_t Qoff  = (uint32_t)32 * QS * 2;

    const int h = blockIdx.x, c = blockIdx.y, b = blockIdx.z;
    const int tid = threadIdx.x, lane = tid & 31, wid = tid >> 5;
    const int qr = lane >> 2, qc = lane & 3;
    const uint32_t ro = (lane & 7) + ((lane >> 3) & 1) * 8;
    const uint32_t co = (lane >> 4) * 8;
    const size_t off = (size_t)b * (T_*D_) + (size_t)c * (128*D_) + (size_t)h * 32 * T;
    const float scale = temp[(tempBase + c) * H_ + h];

    for (int idx = tid; idx < 32 * T; idx += NW * 32) {
        int i = idx / T, t = idx - i * T;
        Khi[t*40 + i] = Kbh[off + idx];
        Klo[t*40 + i] = Kbl[off + idx];
        Vhi[t*40 + i] = Vbh[off + idx];
        Vlo[t*40 + i] = Vbl[off + idx];
        Qhi[i*QS + t] = Qbh[off + idx];
        Qlo[i*QS + t] = Qbl[off + idx];
    }
    __syncthreads();

    const int nb = T >> 4;
    const uint32_t KhiA = smA;
    const uint32_t VhiA = smA + 2 * KVoff;
    const uint32_t QhiA = smA + 4 * KVoff;

    // ---------------- Pass 1: row stats ----------------
    for (int tb = wid; tb < nb; tb += NW) {
        const int t0 = tb * 16;
        unsigned ah[2][4], al[2][4];
#pragma unroll
        for (int ks = 0; ks < 2; ks++) {
            uint32_t ra = KhiA + (((uint32_t)t0 + ro) * 40 + ks*16 + co) * 2;
            ldsm4(ah[ks], ra);
            ldsm4(al[ks], ra + KVoff);
        }
        float m0 = -3.0e38f, m1 = -3.0e38f, l0 = 0.f, l1 = 0.f;
        for (int s0 = 0; s0 < T; s0 += 64) {
            float cc[8][4];
#pragma unroll
            for (int nt = 0; nt < 8; nt++)
#pragma unroll
                for (int j = 0; j < 4; j++) cc[nt][j] = 0.f;
#pragma unroll
            for (int ks = 0; ks < 2; ks++) {
#pragma unroll
                for (int p = 0; p < 4; p++) {
                    uint32_t rv = VhiA + (((uint32_t)(s0 + p*16) + ro) * 40 + ks*16 + co) * 2;
                    unsigned vh4[4], vl4[4];
                    ldsm4(vh4, rv);
                    ldsm4(vl4, rv + KVoff);
                    mma_f16(cc[2*p],   ah[ks], vh4[0], vh4[2]);
                    mma_f16(cc[2*p],   ah[ks], vl4[0], vl4[2]);
                    mma_f16(cc[2*p],   al[ks], vh4[0], vh4[2]);
                    mma_f16(cc[2*p+1], ah[ks], vh4[1], vh4[3]);
                    mma_f16(cc[2*p+1], ah[ks], vl4[1], vl4[3]);
                    mma_f16(cc[2*p+1], al[ks], vh4[1], vh4[3]);
                }
            }
            float cm0 = -3.0e38f, cm1 = -3.0e38f;
#pragma unroll
            for (int nt = 0; nt < 8; nt++) {
#pragma unroll
                for (int j = 0; j < 4; j++) cc[nt][j] *= scale;
                cm0 = fmaxf(cm0, fmaxf(cc[nt][0], cc[nt][1]));
                cm1 = fmaxf(cm1, fmaxf(cc[nt][2], cc[nt][3]));
            }
            cm0 = fmaxf(cm0, __shfl_xor_sync(0xffffffffu, cm0, 1));
            cm0 = fmaxf(cm0, __shfl_xor_sync(0xffffffffu, cm0, 2));
            cm1 = fmaxf(cm1, __shfl_xor_sync(0xffffffffu, cm1, 1));
            cm1 = fmaxf(cm1, __shfl_xor_sync(0xffffffffu, cm1, 2));
            float M0 = fmaxf(m0, cm0), M1 = fmaxf(m1, cm1);
            float p0 = 0.f, p1 = 0.f;
#pragma unroll
            for (int nt = 0; nt < 8; nt++) {
                p0 += __expf(cc[nt][0] - M0) + __expf(cc[nt][1] - M0);
                p1 += __expf(cc[nt][2] - M1) + __expf(cc[nt][3] - M1);
            }
            p0 += __shfl_xor_sync(0xffffffffu, p0, 1);
            p0 += __shfl_xor_sync(0xffffffffu, p0, 2);
            p1 += __shfl_xor_sync(0xffffffffu, p1, 1);
            p1 += __shfl_xor_sync(0xffffffffu, p1, 2);
            l0 = l0 * __expf(m0 - M0) + p0;  m0 = M0;
            l1 = l1 * __expf(m1 - M1) + p1;  m1 = M1;
        }
        if (qc == 0) {
            Mv[t0 + qr]     = m0;  Lv[t0 + qr]     = 1.f / l0;
            Mv[t0 + qr + 8] = m1;  Lv[t0 + qr + 8] = 1.f / l1;
        }
    }
    __syncthreads();

    // ---------------- Pass 2: output ----------------
    __half* Pwh = Pshi + wid * (16 * 24);
    __half* Pwl = Pslo + wid * (16 * 24);
    const uint32_t PwhA = smem_u32(Pwh);
    const uint32_t PwlA = smem_u32(Pwl);
    for (int sb = wid; sb < nb; sb += NW) {
        const int s0 = sb * 16;
        unsigned vh[2][4], vl[2][4];
#pragma unroll
        for (int ks = 0; ks < 2; ks++) {
            uint32_t rv = VhiA + (((uint32_t)s0 + ro) * 40 + ks*16 + co) * 2;
            ldsm4(vh[ks], rv);
            ldsm4(vl[ks], rv + KVoff);
        }
        float o[4][4];
#pragma unroll
        for (int ni = 0; ni < 4; ni++)
#pragma unroll
            for (int j = 0; j < 4; j++) o[ni][j] = 0.f;

        for (int t0 = 0; t0 < T; t0 += 16) {
            float e[2][4];
#pragma unroll
            for (int nt = 0; nt < 2; nt++)
#pragma unroll
                for (int j = 0; j < 4; j++) e[nt][j] = 0.f;
#pragma unroll
            for (int ks = 0; ks < 2; ks++) {
                uint32_t rk = KhiA + (((uint32_t)t0 + ro) * 40 + ks*16 + co) * 2;
                unsigned kh4[4], kl4[4];
                ldsm4(kh4, rk);
                ldsm4(kl4, rk + KVoff);
                mma_f16(e[0], vh[ks], kh4[0], kh4[2]);
                mma_f16(e[0], vh[ks], kl4[0], kl4[2]);
                mma_f16(e[0], vl[ks], kh4[0], kh4[2]);
                mma_f16(e[1], vh[ks], kh4[1], kh4[3]);
                mma_f16(e[1], vh[ks], kl4[1], kl4[3]);
                mma_f16(e[1], vl[ks], kh4[1], kh4[3]);
            }
            __syncwarp();
#pragma unroll
            for (int nt = 0; nt < 2; nt++) {
                int tc = t0 + nt * 8 + 2 * qc;
                float mva = Mv[tc],   lva = Lv[tc];
                float mvb = Mv[tc+1], lvb = Lv[tc+1];
                float e0 = __expf(e[nt][0] * scale - mva) * lva;
                float e1 = __expf(e[nt][1] * scale - mvb) * lvb;
                float e2 = __expf(e[nt][2] * scale - mva) * lva;
                float e3 = __expf(e[nt][3] * scale - mvb) * lvb;
                __half h0, h1, h2, h3, g0, g1, g2, g3;
                split_h(e0, h0, g0); split_h(e1, h1, g1);
                split_h(e2, h2, g2); split_h(e3, h3, g3);
                *(unsigned*)(Pwh + qr*24     + nt*8 + 2*qc) = pack2(h0, h1);
                *(unsigned*)(Pwh + (qr+8)*24 + nt*8 + 2*qc) = pack2(h2, h3);
                *(unsigned*)(Pwl + qr*24     + nt*8 + 2*qc) = pack2(g0, g1);
                *(unsigned*)(Pwl + (qr+8)*24 + nt*8 + 2*qc) = pack2(g2, g3);
            }
            __syncwarp();
            unsigned ph[4], pl[4];
            ldsm4(ph, PwhA + (ro*24 + co) * 2);
            ldsm4(pl, PwlA + (ro*24 + co) * 2);
#pragma unroll
            for (int p2 = 0; p2 < 2; p2++) {
                uint32_t rq = QhiA + ((p2*16 + ro) * (uint32_t)QS + (uint32_t)t0 + co) * 2;
                unsigned q4[4], q4l[4];
                ldsm4(q4,  rq);
                ldsm4(q4l, rq + Qoff);
                mma_f16(o[2*p2],   ph, q4[0], q4[2]);
                mma_f16(o[2*p2],   ph, q4l[0], q4l[2]);
                mma_f16(o[2*p2],   pl, q4[0], q4[2]);
                mma_f16(o[2*p2+1], ph, q4[1], q4[3]);
                mma_f16(o[2*p2+1], ph, q4l[1], q4l[3]);
                mma_f16(o[2*p2+1], pl, q4[1], q4[3]);
            }
        }
#pragma unroll
        for (int ni = 0; ni < 4; ni++) {
            int icol = ni * 8 + 2 * qc;
            int srow = s0 + qr;
            size_t base = off + (size_t)icol * T + srow;
            if (addend != nullptr) {
                Ob[base]         = o[ni][0] + addend[base];
                Ob[base + T]     = o[ni][1] + addend[base + T];
                Ob[base + 8]     = o[ni][2] + addend[base + 8];
                Ob[base + T + 8] = o[ni][3] + addend[base + T + 8];
            } else {
                Ob[base]         = o[ni][0];
                Ob[base + T]     = o[ni][1];
                Ob[base + 8]     = o[ni][2];
                Ob[base + T + 8] = o[ni][3];
            }
        }
    }
}

// ---------------------------------------------------------------------------
// LayerNorm: one warp per 512-wide row; emits split fp16 directly.
// ---------------------------------------------------------------------------
__global__ __launch_bounds__(256) void ln_kernel(
    const float* __restrict__ X, const float* __restrict__ gw,
    const float* __restrict__ gb, __half* __restrict__ Yh, __half* __restrict__ Yl)
{
    const int row  = blockIdx.x * 8 + (threadIdx.x >> 5);
    const int lane = threadIdx.x & 31;
    const float4* xr = (const float4*)(X + (size_t)row * D_);
    float4 v[4];
    float s = 0.f, ss = 0.f;
#pragma unroll
    for (int w = 0; w < 4; w++) {
        v[w] = xr[w*32 + lane];
        s  += v[w].x + v[w].y + v[w].z + v[w].w;
        ss += v[w].x*v[w].x + v[w].y*v[w].y + v[w].z*v[w].z + v[w].w*v[w].w;
    }
#pragma unroll
    for (int o = 16; o > 0; o >>= 1) {
        s  += __shfl_xor_sync(0xffffffffu, s, o);
        ss += __shfl_xor_sync(0xffffffffu, ss, o);
    }
    const float mean = s * (1.f/512.f);
    const float var  = ss * (1.f/512.f) - mean*mean;
    const float r = rsqrtf(var + 1e-5f);
    const float4* gr = (const float4*)gw;
    const float4* br = (const float4*)gb;
#pragma unroll
    for (int w = 0; w < 4; w++) {
        float4 gv = gr[w*32 + lane];
        float4 bv = br[w*32 + lane];
        float o0 = (v[w].x - mean) * r * gv.x + bv.x;
        float o1 = (v[w].y - mean) * r * gv.y + bv.y;
        float o2 = (v[w].z - mean) * r * gv.z + bv.z;
        float o3 = (v[w].w - mean) * r * gv.w + bv.w;
        __half h0,h1,h2,h3,l0,l1,l2,l3;
        split_h(o0,h0,l0); split_h(o1,h1,l1); split_h(o2,h2,l2); split_h(o3,h3,l3);
        size_t idx = (size_t)row * D_ + (w*32 + lane) * 4;
        *(uint2*)(Yh + idx) = make_uint2(pack2(h0,h1), pack2(h2,h3));
        *(uint2*)(Yl + idx) = make_uint2(pack2(l0,l1), pack2(l2,l3));
    }
}

// ---------------------------------------------------------------------------
// Combine: out = t1*sig(ld) + t2*(1-sig(ld)), ld = (t1-t2)@fw^T (bias cancels)
// ---------------------------------------------------------------------------
__global__ __launch_bounds__(256) void fuse2_kernel(
    const float4* __restrict__ t1, const float4* __restrict__ t2,
    const float4* __restrict__ ld, float4* __restrict__ out)
{
    int i = blockIdx.x * 256 + threadIdx.x;
    float4 x1 = t1[i], x2 = t2[i], d = ld[i];
    float a0 = 1.f / (1.f + __expf(-d.x));
    float a1 = 1.f / (1.f + __expf(-d.y));
    float a2 = 1.f / (1.f + __expf(-d.z));
    float a3 = 1.f / (1.f + __expf(-d.w));
    float4 o;
    o.x = x1.x * a0 + x2.x * (1.f - a0);
    o.y = x1.y * a1 + x2.y * (1.f - a1);
    o.z = x1.z * a2 + x2.z * (1.f - a2);
    o.w = x1.w * a3 + x2.w * (1.f - a3);
    out[i] = o;
}

// ---------------------------------------------------------------------------
extern "C" void kernel_launch(void* const* d_in, const int* in_sizes, int n_in,
                              void* d_out, int out_size)
{
    (void)in_sizes; (void)n_in; (void)out_size;
    const float* x    = (const float*)d_in[0];
    const float* qw   = (const float*)d_in[1];
    const float* qb   = (const float*)d_in[2];
    const float* kw   = (const float*)d_in[3];
    const float* kb   = (const float*)d_in[4];
    const float* vw   = (const float*)d_in[5];
    const float* vb   = (const float*)d_in[6];
    const float* temp = (const float*)d_in[7];
    const float* lng  = (const float*)d_in[8];
    const float* lnb  = (const float*)d_in[9];
    const float* fw   = (const float*)d_in[10];
    (void)d_in[11];
    float* out = (float*)d_out;

    float *xr, *t1, *t2, *a1;
    __half *qh,*ql,*kh2,*kl2,*vh2,*vl2, *q2h,*q2l,*k2h,*k2l,*v2h,*v2l;
    __half *xh, *xl, *lnh, *lnl, *dh, *dl, *wh, *wl;
    cudaGetSymbolAddress((void**)&xr, g_xr);
    cudaGetSymbolAddress((void**)&t1, g_t1);
    cudaGetSymbolAddress((void**)&t2, g_t2);
    cudaGetSymbolAddress((void**)&a1, g_a1);
    cudaGetSymbolAddress((void**)&qh, g_qh);   cudaGetSymbolAddress((void**)&ql, g_ql);
    cudaGetSymbolAddress((void**)&kh2, g_kh);  cudaGetSymbolAddress((void**)&kl2, g_kl);
    cudaGetSymbolAddress((void**)&vh2, g_vh);  cudaGetSymbolAddress((void**)&vl2, g_vl);
    cudaGetSymbolAddress((void**)&q2h, g_q2h); cudaGetSymbolAddress((void**)&q2l, g_q2l);
    cudaGetSymbolAddress((void**)&k2h, g_k2h); cudaGetSymbolAddress((void**)&k2l, g_k2l);
    cudaGetSymbolAddress((void**)&v2h, g_v2h); cudaGetSymbolAddress((void**)&v2l, g_v2l);
    cudaGetSymbolAddress((void**)&xh, g_xh);   cudaGetSymbolAddress((void**)&xl, g_xl);
    cudaGetSymbolAddress((void**)&lnh, g_lnh); cudaGetSymbolAddress((void**)&lnl, g_lnl);
    cudaGetSymbolAddress((void**)&dh, g_dh);   cudaGetSymbolAddress((void**)&dl, g_dl);
    cudaGetSymbolAddress((void**)&wh, g_wh);   cudaGetSymbolAddress((void**)&wl, g_wl);

    const int gemmSmem = 3 * STAGE_B;                                          // 184320
    // attn smem: K/V 4*[T][40] + Q 2*[32][T+8] halves + stats + NW*P scratch
    const int smem384 = (4*384*40 + 2*32*392) * 2 + 2*384*4 + (2*12*16*24) * 2;  // 194560
    const int smem128 = (4*128*40 + 2*32*136) * 2 + 2*128*4 + (2*8*16*24) * 2;   // 71680
    cudaFuncSetAttribute(gemm_tc, cudaFuncAttributeMaxDynamicSharedMemorySize, gemmSmem);
    cudaFuncSetAttribute(attn_tc<12>, cudaFuncAttributeMaxDynamicSharedMemorySize, smem384);
    cudaFuncSetAttribute(attn_tc<8>,  cudaFuncAttributeMaxDynamicSharedMemorySize, smem128);

    // 1) pre-split x and all weight matrices
    SpArgs sp1;
    sp1.e[0] = { x,  xh,          xl,          BTD    };
    sp1.e[1] = { qw, wh + 0,      wl + 0,      5*WKN  };
    sp1.e[2] = { kw, wh + (size_t)5*WKN,  wl + (size_t)5*WKN,  5*WKN  };
    sp1.e[3] = { vw, wh + (size_t)10*WKN, wl + (size_t)10*WKN, 5*WKN  };
    sp1.e[4] = { fw, wh + (size_t)15*WKN, wl + (size_t)15*WKN, WKN    };
    split_kernel<<<dim3(512, 1, 5), 256>>>(sp1);

    // 2) QKV GEMMs; Q projections single-fp16 (error enters output linearly)
    G5Args ga1;
    ga1.s[0] = { xh, xl, 0,  0, qb, nullptr, qh,  ql,  0, 0 };
    ga1.s[1] = { xh, xl, 5,  0, kb, nullptr, kh2, kl2, 0, 1 };
    ga1.s[2] = { xh, xl, 10, 0, vb, nullptr, vh2, vl2, 0, 1 };
    ga1.s[3] = { xh, xl, 0,  0, qb, nullptr, q2h, q2l, 1, 0 };
    ga1.s[4] = { xh, xl, 5,  0, kb, nullptr, k2h, k2l, 1, 1 };
    ga1.s[5] = { xh, xl, 10, 0, vb, nullptr, v2h, v2l, 1, 1 };
    gemm_tc<<<dim3(2, 96, 6), 512, gemmSmem>>>(ga1);

    attn_tc<12><<<dim3(H_, 1, B_), 384, smem384>>>(qh, ql, kh2, kl2, vh2, vl2, temp, nullptr, xr, 384, 0);
    attn_tc<8><<<dim3(H_, 3, B_), 256, smem128>>>(q2h, q2l, k2h, k2l, v2h, v2l, temp, xr, t1, 128, 1);

    // 3) LayerNorm(t1) -> split fp16
    ln_kernel<<<M_/8, 256>>>(t1, lng, lnb, lnh, lnl);

    // 4) block4 QKV on LN output (reuse half buffers)
    G5Args ga2;
    ga2.s[0] = { lnh, lnl, 0,  4, qb, nullptr, qh,  ql,  0, 0 };
    ga2.s[1] = { lnh, lnl, 5,  4, kb, nullptr, kh2, kl2, 0, 1 };
    ga2.s[2] = { lnh, lnl, 10, 4, vb, nullptr, vh2, vl2, 0, 1 };
    ga2.s[3] = ga2.s[0]; ga2.s[4] = ga2.s[0]; ga2.s[5] = ga2.s[0];
    gemm_tc<<<dim3(2, 96, 3), 512, gemmSmem>>>(ga2);

    attn_tc<12><<<dim3(H_, 1, B_), 384, smem384>>>(qh, ql, kh2, kl2, vh2, vl2, temp, xr, t2, 384, 4);

    // 5) fusion: single GEMM on the difference (bias cancels in softmax)
    diff_split_kernel<<<BTD/4/256, 256>>>((const float4*)t1, (const float4*)t2, dh, dl);
    G5Args ga3;
    ga3.s[0] = { dh, dl, 15, 0, nullptr, a1, nullptr, nullptr, 0, 0 };
    ga3.s[1] = ga3.s[0]; ga3.s[2] = ga3.s[0]; ga3.s[3] = ga3.s[0];
    ga3.s[4] = ga3.s[0]; ga3.s[5] = ga3.s[0];
    gemm_tc<<<dim3(2, 96, 1), 512, gemmSmem>>>(ga3);

    fuse2_kernel<<<BTD/4/256, 256>>>((const float4*)t1, (const float4*)t2,
                                     (const float4*)a1, (float4*)out);
}

// round 14
// speedup vs baseline: 1.6814x; 1.0360x over previous
#include <cuda_runtime.h>
#include <cuda_fp16.h>
#include <math.h>
#include <stdint.h>

#define B_  32
#define T_  384
#define D_  512
#define H_  16
#define BTD (B_*T_*D_)     // 6291456
#define M_  (B_*T_)        // 12288
#define WKN (512*512)

// ---------------- scratch (static device globals; no cudaMalloc) ----------
__device__ float g_xr[BTD], g_t1[BTD], g_t2[BTD], g_a1[BTD];
__device__ __half g_qh[BTD], g_ql[BTD], g_kh[BTD], g_kl[BTD], g_vh[BTD], g_vl[BTD];
__device__ __half g_q2h[BTD], g_q2l[BTD], g_k2h[BTD], g_k2l[BTD], g_v2h[BTD], g_v2l[BTD];
__device__ __half g_xh[BTD],  g_xl[BTD];
__device__ __half g_lnh[BTD], g_lnl[BTD];
__device__ __half g_dh[BTD],  g_dl[BTD];
__device__ __half g_wh[16*WKN], g_wl[16*WKN];   // [qw0-4 | kw0-4 | vw0-4 | fw]

// ---------------- helpers --------------------------------------------------
__device__ __forceinline__ void split_h(float x, __half& hi, __half& lo) {
    hi = __float2half_rn(x);
    lo = __float2half_rn(x - __half2float(hi));
}
__device__ __forceinline__ unsigned pack2(__half a, __half b) {
    __half2 h = __halves2half2(a, b);
    return *reinterpret_cast<unsigned*>(&h);
}
__device__ __forceinline__ void mma_f16(float* c, const unsigned* a, unsigned b0, unsigned b1) {
    asm volatile("mma.sync.aligned.m16n8k16.row.col.f32.f16.f16.f32 "
        "{%0,%1,%2,%3}, {%4,%5,%6,%7}, {%8,%9}, {%0,%1,%2,%3};"
        : "+f"(c[0]), "+f"(c[1]), "+f"(c[2]), "+f"(c[3])
        : "r"(a[0]), "r"(a[1]), "r"(a[2]), "r"(a[3]), "r"(b0), "r"(b1));
}
__device__ __forceinline__ void ldsm4(unsigned* r, uint32_t addr) {
    asm volatile("ldmatrix.sync.aligned.m8n8.x4.shared.b16 {%0,%1,%2,%3}, [%4];"
        : "=r"(r[0]), "=r"(r[1]), "=r"(r[2]), "=r"(r[3]) : "r"(addr));
}
__device__ __forceinline__ uint32_t smem_u32(const void* p) {
    uint32_t a;
    asm("{ .reg .u64 t; cvta.to.shared.u64 t, %1; cvt.u32.u64 %0, t; }" : "=r"(a) : "l"(p));
    return a;
}
__device__ __forceinline__ void cpa16(uint32_t dst, const void* src) {
    asm volatile("cp.async.cg.shared.global [%0], [%1], 16;" :: "r"(dst), "l"(src) : "memory");
}

// ---------------------------------------------------------------------------
// fp16-split GEMM: CTA tile 128x256, 16 warps at 32x64 each (512 threads),
// k-chunk 32, 3-stage cp.async pipeline, ldmatrix operand loads.
// split=1: 3-mma hi/lo; split=0: single fp16 (hi inputs only).
// ---------------------------------------------------------------------------
#define STAGE_B 61440u    // Ahi 10240 | Alo 10240 | Whi 20480 | Wlo 20480
struct G5 { const __half* Ah; const __half* Al; int wbase; int wadd;
            const float* bias; float* C; __half* Chi; __half* Clo;
            int chunk; int split; };
struct G5Args { G5 s[6]; };

__global__ __launch_bounds__(512) void gemm_tc(G5Args ga)
{
    extern __shared__ __half smh[];
    const uint32_t sm32 = smem_u32(smh);
    const int tid = threadIdx.x, lane = tid & 31, wid = tid >> 5;
    const int wm = wid & 3, wn = wid >> 2;
    const int qr = lane >> 2, qc = lane & 3;
    const uint32_t ro = (lane & 7) + ((lane >> 3) & 1) * 8;
    const uint32_t co = (lane >> 4) * 8;

    const G5 sl = ga.s[blockIdx.z];
    const int m0 = blockIdx.y * 128, n0 = blockIdx.x * 256;
    const int widx = sl.chunk ? (1 + (m0 % 384) / 128) : sl.wadd;
    const __half* Wh = g_wh + (size_t)(sl.wbase + widx) * WKN;
    const __half* Wl = g_wl + (size_t)(sl.wbase + widx) * WKN;
    const float*  bp = sl.bias ? sl.bias + widx * 512 : nullptr;
    const int split = sl.split;

    auto issue = [&](int c) {
        const uint32_t base = sm32 + (uint32_t)(c % 3) * STAGE_B;
        const int kb = c * 32;
        {
            int row = tid >> 2, seg = tid & 3;
            uint32_t d = base + row * 80 + seg * 16;
            size_t gA = (size_t)(m0 + row) * 512 + kb + seg * 8;
            cpa16(d, sl.Ah + gA);
            if (split) cpa16(d + 10240, sl.Al + gA);
        }
#pragma unroll
        for (int r = 0; r < 2; r++) {
            int e = tid + r * 512;
            int row = e >> 2, seg = e & 3;
            uint32_t d = base + 20480 + row * 80 + seg * 16;
            size_t gW = (size_t)(n0 + row) * 512 + kb + seg * 8;
            cpa16(d, Wh + gW);
            if (split) cpa16(d + 20480, Wl + gW);
        }
    };

    float acc[2][8][4];
#pragma unroll
    for (int mi = 0; mi < 2; mi++)
#pragma unroll
        for (int ni = 0; ni < 8; ni++)
#pragma unroll
            for (int j = 0; j < 4; j++) acc[mi][ni][j] = 0.f;

    issue(0);
    asm volatile("cp.async.commit_group;" ::: "memory");
    issue(1);
    asm volatile("cp.async.commit_group;" ::: "memory");

    for (int c = 0; c < 16; c++) {
        asm volatile("cp.async.wait_group 1;" ::: "memory");
        __syncthreads();
        const uint32_t sA = sm32 + (uint32_t)(c % 3) * STAGE_B;
        const uint32_t sW = sA + 20480;
#pragma unroll
        for (int ks = 0; ks < 2; ks++) {
            unsigned ah[2][4], al[2][4];
#pragma unroll
            for (int mi = 0; mi < 2; mi++) {
                uint32_t ra = sA + ((wm*32 + mi*16 + ro) * 40 + ks*16 + co) * 2;
                ldsm4(ah[mi], ra);
                if (split) ldsm4(al[mi], ra + 10240);
            }
#pragma unroll
            for (int p = 0; p < 4; p++) {
                uint32_t rw = sW + ((wn*64 + p*16 + ro) * 40 + ks*16 + co) * 2;
                unsigned wh4[4], wl4[4];
                ldsm4(wh4, rw);
                if (split) ldsm4(wl4, rw + 20480);
#pragma unroll
                for (int mi = 0; mi < 2; mi++) {
                    mma_f16(acc[mi][2*p],   ah[mi], wh4[0], wh4[2]);
                    mma_f16(acc[mi][2*p+1], ah[mi], wh4[1], wh4[3]);
                    if (split) {
                        mma_f16(acc[mi][2*p],   ah[mi], wl4[0], wl4[2]);
                        mma_f16(acc[mi][2*p],   al[mi], wh4[0], wh4[2]);
                        mma_f16(acc[mi][2*p+1], ah[mi], wl4[1], wl4[3]);
                        mma_f16(acc[mi][2*p+1], al[mi], wh4[1], wh4[3]);
                    }
                }
            }
        }
        if (c + 2 < 16) issue(c + 2);
        asm volatile("cp.async.commit_group;" ::: "memory");
    }

    // epilogue
#pragma unroll
    for (int mi = 0; mi < 2; mi++) {
#pragma unroll
        for (int ni = 0; ni < 8; ni++) {
            int row = m0 + wm * 32 + mi * 16 + qr;
            int col = n0 + wn * 64 + ni * 8 + 2 * qc;
            float bx = 0.f, by = 0.f;
            if (bp) { float2 bb = *(const float2*)(bp + col); bx = bb.x; by = bb.y; }
            float v00 = acc[mi][ni][0] + bx, v01 = acc[mi][ni][1] + by;
            float v10 = acc[mi][ni][2] + bx, v11 = acc[mi][ni][3] + by;
            if (sl.Chi) {
                __half h0,h1,l0,l1;
                split_h(v00,h0,l0); split_h(v01,h1,l1);
                *(unsigned*)(sl.Chi + (size_t)row*512 + col) = pack2(h0,h1);
                *(unsigned*)(sl.Clo + (size_t)row*512 + col) = pack2(l0,l1);
                split_h(v10,h0,l0); split_h(v11,h1,l1);
                *(unsigned*)(sl.Chi + (size_t)(row+8)*512 + col) = pack2(h0,h1);
                *(unsigned*)(sl.Clo + (size_t)(row+8)*512 + col) = pack2(l0,l1);
            } else {
                float2 o0 = { v00, v01 }, o1 = { v10, v11 };
                *(float2*)(sl.C + (size_t)row * 512 + col)       = o0;
                *(float2*)(sl.C + (size_t)(row + 8) * 512 + col) = o1;
            }
        }
    }
}

// ---------------------------------------------------------------------------
// split kernels: f32 -> (hi, lo) fp16 pairs
// ---------------------------------------------------------------------------
struct SpEnt { const float* src; __half* hi; __half* lo; int n; };
struct SpArgs { SpEnt e[5]; };

__global__ __launch_bounds__(256) void split_kernel(SpArgs sa)
{
    SpEnt E = sa.e[blockIdx.z];
    int stride = gridDim.x * 256;
    for (int i = blockIdx.x * 256 + threadIdx.x; i * 4 < E.n; i += stride) {
        float4 v = ((const float4*)E.src)[i];
        __half h0,h1,h2,h3,l0,l1,l2,l3;
        split_h(v.x,h0,l0); split_h(v.y,h1,l1); split_h(v.z,h2,l2); split_h(v.w,h3,l3);
        *(uint2*)(E.hi + 4*i) = make_uint2(pack2(h0,h1), pack2(h2,h3));
        *(uint2*)(E.lo + 4*i) = make_uint2(pack2(l0,l1), pack2(l2,l3));
    }
}

__global__ __launch_bounds__(256) void diff_split_kernel(
    const float4* __restrict__ t1, const float4* __restrict__ t2,
    __half* __restrict__ hi, __half* __restrict__ lo)
{
    int i = blockIdx.x * 256 + threadIdx.x;
    float4 a = t1[i], b = t2[i];
    __half h0,h1,h2,h3,l0,l1,l2,l3;
    split_h(a.x-b.x,h0,l0); split_h(a.y-b.y,h1,l1);
    split_h(a.z-b.z,h2,l2); split_h(a.w-b.w,h3,l3);
    *(uint2*)(hi + 4*i) = make_uint2(pack2(h0,h1), pack2(h2,h3));
    *(uint2*)(lo + 4*i) = make_uint2(pack2(l0,l1), pack2(l2,l3));
}

// ---------------------------------------------------------------------------
// Two-pass fp16-split attention with ldmatrix operand loads, templated on
// warp count NW. K/V tiles [T][40], Q [32][QS]. Pass loops stride by NW;
// P scratch is per-warp [16][24].
// ---------------------------------------------------------------------------
template<int NW>
__global__ __launch_bounds__(32*NW) void attn_tc(
    const __half* __restrict__ Qbh, const __half* __restrict__ Qbl,
    const __half* __restrict__ Kbh, const __half* __restrict__ Kbl,
    const __half* __restrict__ Vbh, const __half* __restrict__ Vbl,
    const float* __restrict__ temp,
    const float* __restrict__ addend, float* __restrict__ Ob,
    int T, int tempBase)
{
    extern __shared__ __half smh[];
    const int QS = T + 8;
    __half* Khi = smh;                       // [T][40]
    __half* Klo = Khi + T * 40;
    __half* Vhi = Klo + T * 40;
    __half* Vlo = Vhi + T * 40;
    __half* Qhi = Vlo + T * 40;              // [32][QS]
    __half* Qlo = Qhi + 32 * QS;
    float*  Mv  = (float*)(Qlo + 32 * QS);
    float*  Lv  = Mv + T;
    __half* Pshi = (__half*)(Lv + T);        // NW warps * [16][24]
    __half* Pslo = Pshi + NW * 16 * 24;

    const uint32_t smA   = smem_u32(smh);
    const uint32_t KVoff = (uint32_t)T * 80;
    const uint32_t Qoff  = (uint32_t)32 * QS * 2;

    const int h = blockIdx.x, c = blockIdx.y, b = blockIdx.z;
    const int tid = threadIdx.x, lane = tid & 31, wid = tid >> 5;
    const int qr = lane >> 2, qc = lane & 3;
    const uint32_t ro = (lane & 7) + ((lane >> 3) & 1) * 8;
    const uint32_t co = (lane >> 4) * 8;
    const size_t off = (size_t)b * (T_*D_) + (size_t)c * (128*D_) + (size_t)h * 32 * T;
    const float scale = temp[(tempBase + c) * H_ + h];

    for (int idx = tid; idx < 32 * T; idx += NW * 32) {
        int i = idx / T, t = idx - i * T;
        Khi[t*40 + i] = Kbh[off + idx];
        Klo[t*40 + i] = Kbl[off + idx];
        Vhi[t*40 + i] = Vbh[off + idx];
        Vlo[t*40 + i] = Vbl[off + idx];
        Qhi[i*QS + t] = Qbh[off + idx];
        Qlo[i*QS + t] = Qbl[off + idx];
    }
    __syncthreads();

    const int nb = T >> 4;
    const uint32_t KhiA = smA;
    const uint32_t VhiA = smA + 2 * KVoff;
    const uint32_t QhiA = smA + 4 * KVoff;

    // ---------------- Pass 1: row stats ----------------
    for (int tb = wid; tb < nb; tb += NW) {
        const int t0 = tb * 16;
        unsigned ah[2][4], al[2][4];
#pragma unroll
        for (int ks = 0; ks < 2; ks++) {
            uint32_t ra = KhiA + (((uint32_t)t0 + ro) * 40 + ks*16 + co) * 2;
            ldsm4(ah[ks], ra);
            ldsm4(al[ks], ra + KVoff);
        }
        float m0 = -3.0e38f, m1 = -3.0e38f, l0 = 0.f, l1 = 0.f;
        for (int s0 = 0; s0 < T; s0 += 64) {
            float cc[8][4];
#pragma unroll
            for (int nt = 0; nt < 8; nt++)
#pragma unroll
                for (int j = 0; j < 4; j++) cc[nt][j] = 0.f;
#pragma unroll
            for (int ks = 0; ks < 2; ks++) {
#pragma unroll
                for (int p = 0; p < 4; p++) {
                    uint32_t rv = VhiA + (((uint32_t)(s0 + p*16) + ro) * 40 + ks*16 + co) * 2;
                    unsigned vh4[4], vl4[4];
                    ldsm4(vh4, rv);
                    ldsm4(vl4, rv + KVoff);
                    mma_f16(cc[2*p],   ah[ks], vh4[0], vh4[2]);
                    mma_f16(cc[2*p],   ah[ks], vl4[0], vl4[2]);
                    mma_f16(cc[2*p],   al[ks], vh4[0], vh4[2]);
                    mma_f16(cc[2*p+1], ah[ks], vh4[1], vh4[3]);
                    mma_f16(cc[2*p+1], ah[ks], vl4[1], vl4[3]);
                    mma_f16(cc[2*p+1], al[ks], vh4[1], vh4[3]);
                }
            }
            float cm0 = -3.0e38f, cm1 = -3.0e38f;
#pragma unroll
            for (int nt = 0; nt < 8; nt++) {
#pragma unroll
                for (int j = 0; j < 4; j++) cc[nt][j] *= scale;
                cm0 = fmaxf(cm0, fmaxf(cc[nt][0], cc[nt][1]));
                cm1 = fmaxf(cm1, fmaxf(cc[nt][2], cc[nt][3]));
            }
            cm0 = fmaxf(cm0, __shfl_xor_sync(0xffffffffu, cm0, 1));
            cm0 = fmaxf(cm0, __shfl_xor_sync(0xffffffffu, cm0, 2));
            cm1 = fmaxf(cm1, __shfl_xor_sync(0xffffffffu, cm1, 1));
            cm1 = fmaxf(cm1, __shfl_xor_sync(0xffffffffu, cm1, 2));
            float M0 = fmaxf(m0, cm0), M1 = fmaxf(m1, cm1);
            float p0 = 0.f, p1 = 0.f;
#pragma unroll
            for (int nt = 0; nt < 8; nt++) {
                p0 += __expf(cc[nt][0] - M0) + __expf(cc[nt][1] - M0);
                p1 += __expf(cc[nt][2] - M1) + __expf(cc[nt][3] - M1);
            }
            p0 += __shfl_xor_sync(0xffffffffu, p0, 1);
            p0 += __shfl_xor_sync(0xffffffffu, p0, 2);
            p1 += __shfl_xor_sync(0xffffffffu, p1, 1);
            p1 += __shfl_xor_sync(0xffffffffu, p1, 2);
            l0 = l0 * __expf(m0 - M0) + p0;  m0 = M0;
            l1 = l1 * __expf(m1 - M1) + p1;  m1 = M1;
        }
        if (qc == 0) {
            Mv[t0 + qr]     = m0;  Lv[t0 + qr]     = 1.f / l0;
            Mv[t0 + qr + 8] = m1;  Lv[t0 + qr + 8] = 1.f / l1;
        }
    }
    __syncthreads();

    // ---------------- Pass 2: output ----------------
    __half* Pwh = Pshi + wid * (16 * 24);
    __half* Pwl = Pslo + wid * (16 * 24);
    const uint32_t PwhA = smem_u32(Pwh);
    const uint32_t PwlA = smem_u32(Pwl);
    for (int sb = wid; sb < nb; sb += NW) {
        const int s0 = sb * 16;
        unsigned vh[2][4], vl[2][4];
#pragma unroll
        for (int ks = 0; ks < 2; ks++) {
            uint32_t rv = VhiA + (((uint32_t)s0 + ro) * 40 + ks*16 + co) * 2;
            ldsm4(vh[ks], rv);
            ldsm4(vl[ks], rv + KVoff);
        }
        float o[4][4];
#pragma unroll
        for (int ni = 0; ni < 4; ni++)
#pragma unroll
            for (int j = 0; j < 4; j++) o[ni][j] = 0.f;

        for (int t0 = 0; t0 < T; t0 += 16) {
            float e[2][4];
#pragma unroll
            for (int nt = 0; nt < 2; nt++)
#pragma unroll
                for (int j = 0; j < 4; j++) e[nt][j] = 0.f;
#pragma unroll
            for (int ks = 0; ks < 2; ks++) {
                uint32_t rk = KhiA + (((uint32_t)t0 + ro) * 40 + ks*16 + co) * 2;
                unsigned kh4[4], kl4[4];
                ldsm4(kh4, rk);
                ldsm4(kl4, rk + KVoff);
                mma_f16(e[0], vh[ks], kh4[0], kh4[2]);
                mma_f16(e[0], vh[ks], kl4[0], kl4[2]);
                mma_f16(e[0], vl[ks], kh4[0], kh4[2]);
                mma_f16(e[1], vh[ks], kh4[1], kh4[3]);
                mma_f16(e[1], vh[ks], kl4[1], kl4[3]);
                mma_f16(e[1], vl[ks], kh4[1], kh4[3]);
            }
            __syncwarp();
#pragma unroll
            for (int nt = 0; nt < 2; nt++) {
                int tc = t0 + nt * 8 + 2 * qc;
                float mva = Mv[tc],   lva = Lv[tc];
                float mvb = Mv[tc+1], lvb = Lv[tc+1];
                float e0 = __expf(e[nt][0] * scale - mva) * lva;
                float e1 = __expf(e[nt][1] * scale - mvb) * lvb;
                float e2 = __expf(e[nt][2] * scale - mva) * lva;
                float e3 = __expf(e[nt][3] * scale - mvb) * lvb;
                __half h0, h1, h2, h3, g0, g1, g2, g3;
                split_h(e0, h0, g0); split_h(e1, h1, g1);
                split_h(e2, h2, g2); split_h(e3, h3, g3);
                *(unsigned*)(Pwh + qr*24     + nt*8 + 2*qc) = pack2(h0, h1);
                *(unsigned*)(Pwh + (qr+8)*24 + nt*8 + 2*qc) = pack2(h2, h3);
                *(unsigned*)(Pwl + qr*24     + nt*8 + 2*qc) = pack2(g0, g1);
                *(unsigned*)(Pwl + (qr+8)*24 + nt*8 + 2*qc) = pack2(g2, g3);
            }
            __syncwarp();
            unsigned ph[4], pl[4];
            ldsm4(ph, PwhA + (ro*24 + co) * 2);
            ldsm4(pl, PwlA + (ro*24 + co) * 2);
#pragma unroll
            for (int p2 = 0; p2 < 2; p2++) {
                uint32_t rq = QhiA + ((p2*16 + ro) * (uint32_t)QS + (uint32_t)t0 + co) * 2;
                unsigned q4[4], q4l[4];
                ldsm4(q4,  rq);
                ldsm4(q4l, rq + Qoff);
                mma_f16(o[2*p2],   ph, q4[0], q4[2]);
                mma_f16(o[2*p2],   ph, q4l[0], q4l[2]);
                mma_f16(o[2*p2],   pl, q4[0], q4[2]);
                mma_f16(o[2*p2+1], ph, q4[1], q4[3]);
                mma_f16(o[2*p2+1], ph, q4l[1], q4l[3]);
                mma_f16(o[2*p2+1], pl, q4[1], q4[3]);
            }
        }
#pragma unroll
        for (int ni = 0; ni < 4; ni++) {
            int icol = ni * 8 + 2 * qc;
            int srow = s0 + qr;
            size_t base = off + (size_t)icol * T + srow;
            if (addend != nullptr) {
                Ob[base]         = o[ni][0] + addend[base];
                Ob[base + T]     = o[ni][1] + addend[base + T];
                Ob[base + 8]     = o[ni][2] + addend[base + 8];
                Ob[base + T + 8] = o[ni][3] + addend[base + T + 8];
            } else {
                Ob[base]         = o[ni][0];
                Ob[base + T]     = o[ni][1];
                Ob[base + 8]     = o[ni][2];
                Ob[base + T + 8] = o[ni][3];
            }
        }
    }
}

// ---------------------------------------------------------------------------
// LayerNorm: one warp per 512-wide row; emits split fp16 directly.
// ---------------------------------------------------------------------------
__global__ __launch_bounds__(256) void ln_kernel(
    const float* __restrict__ X, const float* __restrict__ gw,
    const float* __restrict__ gb, __half* __restrict__ Yh, __half* __restrict__ Yl)
{
    const int row  = blockIdx.x * 8 + (threadIdx.x >> 5);
    const int lane = threadIdx.x & 31;
    const float4* xr = (const float4*)(X + (size_t)row * D_);
    float4 v[4];
    float s = 0.f, ss = 0.f;
#pragma unroll
    for (int w = 0; w < 4; w++) {
        v[w] = xr[w*32 + lane];
        s  += v[w].x + v[w].y + v[w].z + v[w].w;
        ss += v[w].x*v[w].x + v[w].y*v[w].y + v[w].z*v[w].z + v[w].w*v[w].w;
    }
#pragma unroll
    for (int o = 16; o > 0; o >>= 1) {
        s  += __shfl_xor_sync(0xffffffffu, s, o);
        ss += __shfl_xor_sync(0xffffffffu, ss, o);
    }
    const float mean = s * (1.f/512.f);
    const float var  = ss * (1.f/512.f) - mean*mean;
    const float r = rsqrtf(var + 1e-5f);
    const float4* gr = (const float4*)gw;
    const float4* br = (const float4*)gb;
#pragma unroll
    for (int w = 0; w < 4; w++) {
        float4 gv = gr[w*32 + lane];
        float4 bv = br[w*32 + lane];
        float o0 = (v[w].x - mean) * r * gv.x + bv.x;
        float o1 = (v[w].y - mean) * r * gv.y + bv.y;
        float o2 = (v[w].z - mean) * r * gv.z + bv.z;
        float o3 = (v[w].w - mean) * r * gv.w + bv.w;
        __half h0,h1,h2,h3,l0,l1,l2,l3;
        split_h(o0,h0,l0); split_h(o1,h1,l1); split_h(o2,h2,l2); split_h(o3,h3,l3);
        size_t idx = (size_t)row * D_ + (w*32 + lane) * 4;
        *(uint2*)(Yh + idx) = make_uint2(pack2(h0,h1), pack2(h2,h3));
        *(uint2*)(Yl + idx) = make_uint2(pack2(l0,l1), pack2(l2,l3));
    }
}

// ---------------------------------------------------------------------------
// Combine: out = t1*sig(ld) + t2*(1-sig(ld)), ld = (t1-t2)@fw^T (bias cancels)
// ---------------------------------------------------------------------------
__global__ __launch_bounds__(256) void fuse2_kernel(
    const float4* __restrict__ t1, const float4* __restrict__ t2,
    const float4* __restrict__ ld, float4* __restrict__ out)
{
    int i = blockIdx.x * 256 + threadIdx.x;
    float4 x1 = t1[i], x2 = t2[i], d = ld[i];
    float a0 = 1.f / (1.f + __expf(-d.x));
    float a1 = 1.f / (1.f + __expf(-d.y));
    float a2 = 1.f / (1.f + __expf(-d.z));
    float a3 = 1.f / (1.f + __expf(-d.w));
    float4 o;
    o.x = x1.x * a0 + x2.x * (1.f - a0);
    o.y = x1.y * a1 + x2.y * (1.f - a1);
    o.z = x1.z * a2 + x2.z * (1.f - a2);
    o.w = x1.w * a3 + x2.w * (1.f - a3);
    out[i] = o;
}

// ---------------------------------------------------------------------------
extern "C" void kernel_launch(void* const* d_in, const int* in_sizes, int n_in,
                              void* d_out, int out_size)
{
    (void)in_sizes; (void)n_in; (void)out_size;
    const float* x    = (const float*)d_in[0];
    const float* qw   = (const float*)d_in[1];
    const float* qb   = (const float*)d_in[2];
    const float* kw   = (const float*)d_in[3];
    const float* kb   = (const float*)d_in[4];
    const float* vw   = (const float*)d_in[5];
    const float* vb   = (const float*)d_in[6];
    const float* temp = (const float*)d_in[7];
    const float* lng  = (const float*)d_in[8];
    const float* lnb  = (const float*)d_in[9];
    const float* fw   = (const float*)d_in[10];
    (void)d_in[11];
    float* out = (float*)d_out;

    float *xr, *t1, *t2, *a1;
    __half *qh,*ql,*kh2,*kl2,*vh2,*vl2, *q2h,*q2l,*k2h,*k2l,*v2h,*v2l;
    __half *xh, *xl, *lnh, *lnl, *dh, *dl, *wh, *wl;
    cudaGetSymbolAddress((void**)&xr, g_xr);
    cudaGetSymbolAddress((void**)&t1, g_t1);
    cudaGetSymbolAddress((void**)&t2, g_t2);
    cudaGetSymbolAddress((void**)&a1, g_a1);
    cudaGetSymbolAddress((void**)&qh, g_qh);   cudaGetSymbolAddress((void**)&ql, g_ql);
    cudaGetSymbolAddress((void**)&kh2, g_kh);  cudaGetSymbolAddress((void**)&kl2, g_kl);
    cudaGetSymbolAddress((void**)&vh2, g_vh);  cudaGetSymbolAddress((void**)&vl2, g_vl);
    cudaGetSymbolAddress((void**)&q2h, g_q2h); cudaGetSymbolAddress((void**)&q2l, g_q2l);
    cudaGetSymbolAddress((void**)&k2h, g_k2h); cudaGetSymbolAddress((void**)&k2l, g_k2l);
    cudaGetSymbolAddress((void**)&v2h, g_v2h); cudaGetSymbolAddress((void**)&v2l, g_v2l);
    cudaGetSymbolAddress((void**)&xh, g_xh);   cudaGetSymbolAddress((void**)&xl, g_xl);
    cudaGetSymbolAddress((void**)&lnh, g_lnh); cudaGetSymbolAddress((void**)&lnl, g_lnl);
    cudaGetSymbolAddress((void**)&dh, g_dh);   cudaGetSymbolAddress((void**)&dl, g_dl);
    cudaGetSymbolAddress((void**)&wh, g_wh);   cudaGetSymbolAddress((void**)&wl, g_wl);

    const int gemmSmem = 3 * STAGE_B;                                            // 184320
    // attn smem: K/V 4*[T][40] + Q 2*[32][T+8] halves + stats + NW*P scratch
    const int smem384 = (4*384*40 + 2*32*392) * 2 + 2*384*4 + (2*24*16*24) * 2;  // 212992
    const int smem128 = (4*128*40 + 2*32*136) * 2 + 2*128*4 + (2*8*16*24) * 2;   // 71680
    cudaFuncSetAttribute(gemm_tc, cudaFuncAttributeMaxDynamicSharedMemorySize, gemmSmem);
    cudaFuncSetAttribute(attn_tc<24>, cudaFuncAttributeMaxDynamicSharedMemorySize, smem384);
    cudaFuncSetAttribute(attn_tc<8>,  cudaFuncAttributeMaxDynamicSharedMemorySize, smem128);

    // 1) pre-split x and all weight matrices
    SpArgs sp1;
    sp1.e[0] = { x,  xh,          xl,          BTD    };
    sp1.e[1] = { qw, wh + 0,      wl + 0,      5*WKN  };
    sp1.e[2] = { kw, wh + (size_t)5*WKN,  wl + (size_t)5*WKN,  5*WKN  };
    sp1.e[3] = { vw, wh + (size_t)10*WKN, wl + (size_t)10*WKN, 5*WKN  };
    sp1.e[4] = { fw, wh + (size_t)15*WKN, wl + (size_t)15*WKN, WKN    };
    split_kernel<<<dim3(512, 1, 5), 256>>>(sp1);

    // 2) QKV GEMMs; Q projections single-fp16 (error enters output linearly)
    G5Args ga1;
    ga1.s[0] = { xh, xl, 0,  0, qb, nullptr, qh,  ql,  0, 0 };
    ga1.s[1] = { xh, xl, 5,  0, kb, nullptr, kh2, kl2, 0, 1 };
    ga1.s[2] = { xh, xl, 10, 0, vb, nullptr, vh2, vl2, 0, 1 };
    ga1.s[3] = { xh, xl, 0,  0, qb, nullptr, q2h, q2l, 1, 0 };
    ga1.s[4] = { xh, xl, 5,  0, kb, nullptr, k2h, k2l, 1, 1 };
    ga1.s[5] = { xh, xl, 10, 0, vb, nullptr, v2h, v2l, 1, 1 };
    gemm_tc<<<dim3(2, 96, 6), 512, gemmSmem>>>(ga1);

    attn_tc<24><<<dim3(H_, 1, B_), 768, smem384>>>(qh, ql, kh2, kl2, vh2, vl2, temp, nullptr, xr, 384, 0);
    attn_tc<8><<<dim3(H_, 3, B_), 256, smem128>>>(q2h, q2l, k2h, k2l, v2h, v2l, temp, xr, t1, 128, 1);

    // 3) LayerNorm(t1) -> split fp16
    ln_kernel<<<M_/8, 256>>>(t1, lng, lnb, lnh, lnl);

    // 4) block4 QKV on LN output (reuse half buffers)
    G5Args ga2;
    ga2.s[0] = { lnh, lnl, 0,  4, qb, nullptr, qh,  ql,  0, 0 };
    ga2.s[1] = { lnh, lnl, 5,  4, kb, nullptr, kh2, kl2, 0, 1 };
    ga2.s[2] = { lnh, lnl, 10, 4, vb, nullptr, vh2, vl2, 0, 1 };
    ga2.s[3] = ga2.s[0]; ga2.s[4] = ga2.s[0]; ga2.s[5] = ga2.s[0];
    gemm_tc<<<dim3(2, 96, 3), 512, gemmSmem>>>(ga2);

    attn_tc<24><<<dim3(H_, 1, B_), 768, smem384>>>(qh, ql, kh2, kl2, vh2, vl2, temp, xr, t2, 384, 4);

    // 5) fusion: single GEMM on the difference (bias cancels in softmax)
    diff_split_kernel<<<BTD/4/256, 256>>>((const float4*)t1, (const float4*)t2, dh, dl);
    G5Args ga3;
    ga3.s[0] = { dh, dl, 15, 0, nullptr, a1, nullptr, nullptr, 0, 0 };
    ga3.s[1] = ga3.s[0]; ga3.s[2] = ga3.s[0]; ga3.s[3] = ga3.s[0];
    ga3.s[4] = ga3.s[0]; ga3.s[5] = ga3.s[0];
    gemm_tc<<<dim3(2, 96, 1), 512, gemmSmem>>>(ga3);

    fuse2_kernel<<<BTD/4/256, 256>>>((const float4*)t1, (const float4*)t2,
                                     (const float4*)a1, (float4*)out);
}

// round 15
// speedup vs baseline: 1.8380x; 1.0931x over previous
#include <cuda_runtime.h>
#include <cuda_fp16.h>
#include <math.h>
#include <stdint.h>

#define B_  32
#define T_  384
#define D_  512
#define H_  16
#define BTD (B_*T_*D_)     // 6291456
#define M_  (B_*T_)        // 12288
#define WKN (512*512)

// ---------------- scratch (static device globals; no cudaMalloc) ----------
__device__ float g_xr[BTD], g_t1[BTD], g_t2[BTD], g_a1[BTD];
__device__ __half g_qh[BTD], g_ql[BTD], g_kh[BTD], g_kl[BTD], g_vh[BTD], g_vl[BTD];
__device__ __half g_q2h[BTD], g_q2l[BTD], g_k2h[BTD], g_k2l[BTD], g_v2h[BTD], g_v2l[BTD];
__device__ __half g_xh[BTD],  g_xl[BTD];
__device__ __half g_lnh[BTD], g_lnl[BTD];
__device__ __half g_dh[BTD],  g_dl[BTD];
__device__ __half g_wh[16*WKN], g_wl[16*WKN];   // [qw0-4 | kw0-4 | vw0-4 | fw]

// ---------------- helpers --------------------------------------------------
__device__ __forceinline__ void split_h(float x, __half& hi, __half& lo) {
    hi = __float2half_rn(x);
    lo = __float2half_rn(x - __half2float(hi));
}
__device__ __forceinline__ unsigned pack2(__half a, __half b) {
    __half2 h = __halves2half2(a, b);
    return *reinterpret_cast<unsigned*>(&h);
}
__device__ __forceinline__ void mma_f16(float* c, const unsigned* a, unsigned b0, unsigned b1) {
    asm volatile("mma.sync.aligned.m16n8k16.row.col.f32.f16.f16.f32 "
        "{%0,%1,%2,%3}, {%4,%5,%6,%7}, {%8,%9}, {%0,%1,%2,%3};"
        : "+f"(c[0]), "+f"(c[1]), "+f"(c[2]), "+f"(c[3])
        : "r"(a[0]), "r"(a[1]), "r"(a[2]), "r"(a[3]), "r"(b0), "r"(b1));
}
__device__ __forceinline__ void ldsm4(unsigned* r, uint32_t addr) {
    asm volatile("ldmatrix.sync.aligned.m8n8.x4.shared.b16 {%0,%1,%2,%3}, [%4];"
        : "=r"(r[0]), "=r"(r[1]), "=r"(r[2]), "=r"(r[3]) : "r"(addr));
}
__device__ __forceinline__ uint32_t smem_u32(const void* p) {
    uint32_t a;
    asm("{ .reg .u64 t; cvta.to.shared.u64 t, %1; cvt.u32.u64 %0, t; }" : "=r"(a) : "l"(p));
    return a;
}
__device__ __forceinline__ void cpa16(uint32_t dst, const void* src) {
    asm volatile("cp.async.cg.shared.global [%0], [%1], 16;" :: "r"(dst), "l"(src) : "memory");
}

// ---------------------------------------------------------------------------
// fp16-split GEMM: CTA tile 128x256, 16 warps at 32x64 each (512 threads),
// k-chunk 32, 3-stage cp.async pipeline, ldmatrix operand loads.
// split=1: 3-mma hi/lo; split=0: single fp16 (hi inputs only).
// mma emission rotated across accumulators (same-acc distance 4); per-acc
// term order (hh,hl,lh) preserved -> numerically identical to R14.
// ---------------------------------------------------------------------------
#define STAGE_B 61440u    // Ahi 10240 | Alo 10240 | Whi 20480 | Wlo 20480
struct G5 { const __half* Ah; const __half* Al; int wbase; int wadd;
            const float* bias; float* C; __half* Chi; __half* Clo;
            int chunk; int split; };
struct G5Args { G5 s[6]; };

__global__ __launch_bounds__(512) void gemm_tc(G5Args ga)
{
    extern __shared__ __half smh[];
    const uint32_t sm32 = smem_u32(smh);
    const int tid = threadIdx.x, lane = tid & 31, wid = tid >> 5;
    const int wm = wid & 3, wn = wid >> 2;
    const int qr = lane >> 2, qc = lane & 3;
    const uint32_t ro = (lane & 7) + ((lane >> 3) & 1) * 8;
    const uint32_t co = (lane >> 4) * 8;

    const G5 sl = ga.s[blockIdx.z];
    const int m0 = blockIdx.y * 128, n0 = blockIdx.x * 256;
    const int widx = sl.chunk ? (1 + (m0 % 384) / 128) : sl.wadd;
    const __half* Wh = g_wh + (size_t)(sl.wbase + widx) * WKN;
    const __half* Wl = g_wl + (size_t)(sl.wbase + widx) * WKN;
    const float*  bp = sl.bias ? sl.bias + widx * 512 : nullptr;
    const int split = sl.split;

    auto issue = [&](int c) {
        const uint32_t base = sm32 + (uint32_t)(c % 3) * STAGE_B;
        const int kb = c * 32;
        {
            int row = tid >> 2, seg = tid & 3;
            uint32_t d = base + row * 80 + seg * 16;
            size_t gA = (size_t)(m0 + row) * 512 + kb + seg * 8;
            cpa16(d, sl.Ah + gA);
            if (split) cpa16(d + 10240, sl.Al + gA);
        }
#pragma unroll
        for (int r = 0; r < 2; r++) {
            int e = tid + r * 512;
            int row = e >> 2, seg = e & 3;
            uint32_t d = base + 20480 + row * 80 + seg * 16;
            size_t gW = (size_t)(n0 + row) * 512 + kb + seg * 8;
            cpa16(d, Wh + gW);
            if (split) cpa16(d + 20480, Wl + gW);
        }
    };

    float acc[2][8][4];
#pragma unroll
    for (int mi = 0; mi < 2; mi++)
#pragma unroll
        for (int ni = 0; ni < 8; ni++)
#pragma unroll
            for (int j = 0; j < 4; j++) acc[mi][ni][j] = 0.f;

    issue(0);
    asm volatile("cp.async.commit_group;" ::: "memory");
    issue(1);
    asm volatile("cp.async.commit_group;" ::: "memory");

    for (int c = 0; c < 16; c++) {
        asm volatile("cp.async.wait_group 1;" ::: "memory");
        __syncthreads();
        const uint32_t sA = sm32 + (uint32_t)(c % 3) * STAGE_B;
        const uint32_t sW = sA + 20480;
#pragma unroll
        for (int ks = 0; ks < 2; ks++) {
            unsigned ah[2][4], al[2][4];
#pragma unroll
            for (int mi = 0; mi < 2; mi++) {
                uint32_t ra = sA + ((wm*32 + mi*16 + ro) * 40 + ks*16 + co) * 2;
                ldsm4(ah[mi], ra);
                if (split) ldsm4(al[mi], ra + 10240);
            }
#pragma unroll
            for (int p = 0; p < 4; p++) {
                uint32_t rw = sW + ((wn*64 + p*16 + ro) * 40 + ks*16 + co) * 2;
                unsigned wh4[4], wl4[4];
                ldsm4(wh4, rw);
                if (split) ldsm4(wl4, rw + 20480);
                // term hh across 4 accs (distance 4)
#pragma unroll
                for (int mi = 0; mi < 2; mi++) {
                    mma_f16(acc[mi][2*p],   ah[mi], wh4[0], wh4[2]);
                    mma_f16(acc[mi][2*p+1], ah[mi], wh4[1], wh4[3]);
                }
                if (split) {
                    // term hl across 4 accs
#pragma unroll
                    for (int mi = 0; mi < 2; mi++) {
                        mma_f16(acc[mi][2*p],   ah[mi], wl4[0], wl4[2]);
                        mma_f16(acc[mi][2*p+1], ah[mi], wl4[1], wl4[3]);
                    }
                    // term lh across 4 accs
#pragma unroll
                    for (int mi = 0; mi < 2; mi++) {
                        mma_f16(acc[mi][2*p],   al[mi], wh4[0], wh4[2]);
                        mma_f16(acc[mi][2*p+1], al[mi], wh4[1], wh4[3]);
                    }
                }
            }
        }
        if (c + 2 < 16) issue(c + 2);
        asm volatile("cp.async.commit_group;" ::: "memory");
    }

    // epilogue
#pragma unroll
    for (int mi = 0; mi < 2; mi++) {
#pragma unroll
        for (int ni = 0; ni < 8; ni++) {
            int row = m0 + wm * 32 + mi * 16 + qr;
            int col = n0 + wn * 64 + ni * 8 + 2 * qc;
            float bx = 0.f, by = 0.f;
            if (bp) { float2 bb = *(const float2*)(bp + col); bx = bb.x; by = bb.y; }
            float v00 = acc[mi][ni][0] + bx, v01 = acc[mi][ni][1] + by;
            float v10 = acc[mi][ni][2] + bx, v11 = acc[mi][ni][3] + by;
            if (sl.Chi) {
                __half h0,h1,l0,l1;
                split_h(v00,h0,l0); split_h(v01,h1,l1);
                *(unsigned*)(sl.Chi + (size_t)row*512 + col) = pack2(h0,h1);
                *(unsigned*)(sl.Clo + (size_t)row*512 + col) = pack2(l0,l1);
                split_h(v10,h0,l0); split_h(v11,h1,l1);
                *(unsigned*)(sl.Chi + (size_t)(row+8)*512 + col) = pack2(h0,h1);
                *(unsigned*)(sl.Clo + (size_t)(row+8)*512 + col) = pack2(l0,l1);
            } else {
                float2 o0 = { v00, v01 }, o1 = { v10, v11 };
                *(float2*)(sl.C + (size_t)row * 512 + col)       = o0;
                *(float2*)(sl.C + (size_t)(row + 8) * 512 + col) = o1;
            }
        }
    }
}

// ---------------------------------------------------------------------------
// split kernels: f32 -> (hi, lo) fp16 pairs
// ---------------------------------------------------------------------------
struct SpEnt { const float* src; __half* hi; __half* lo; int n; };
struct SpArgs { SpEnt e[5]; };

__global__ __launch_bounds__(256) void split_kernel(SpArgs sa)
{
    SpEnt E = sa.e[blockIdx.z];
    int stride = gridDim.x * 256;
    for (int i = blockIdx.x * 256 + threadIdx.x; i * 4 < E.n; i += stride) {
        float4 v = ((const float4*)E.src)[i];
        __half h0,h1,h2,h3,l0,l1,l2,l3;
        split_h(v.x,h0,l0); split_h(v.y,h1,l1); split_h(v.z,h2,l2); split_h(v.w,h3,l3);
        *(uint2*)(E.hi + 4*i) = make_uint2(pack2(h0,h1), pack2(h2,h3));
        *(uint2*)(E.lo + 4*i) = make_uint2(pack2(l0,l1), pack2(l2,l3));
    }
}

__global__ __launch_bounds__(256) void diff_split_kernel(
    const float4* __restrict__ t1, const float4* __restrict__ t2,
    __half* __restrict__ hi, __half* __restrict__ lo)
{
    int i = blockIdx.x * 256 + threadIdx.x;
    float4 a = t1[i], b = t2[i];
    __half h0,h1,h2,h3,l0,l1,l2,l3;
    split_h(a.x-b.x,h0,l0); split_h(a.y-b.y,h1,l1);
    split_h(a.z-b.z,h2,l2); split_h(a.w-b.w,h3,l3);
    *(uint2*)(hi + 4*i) = make_uint2(pack2(h0,h1), pack2(h2,h3));
    *(uint2*)(lo + 4*i) = make_uint2(pack2(l0,l1), pack2(l2,l3));
}

// ---------------------------------------------------------------------------
// Two-pass fp16-split attention with ldmatrix operand loads, templated on
// warp count NW. K/V tiles [T][40], Q [32][QS]. Pass loops stride by NW;
// P scratch per-warp [16][24]. mma emission rotated across accumulators.
// ---------------------------------------------------------------------------
template<int NW>
__global__ __launch_bounds__(32*NW) void attn_tc(
    const __half* __restrict__ Qbh, const __half* __restrict__ Qbl,
    const __half* __restrict__ Kbh, const __half* __restrict__ Kbl,
    const __half* __restrict__ Vbh, const __half* __restrict__ Vbl,
    const float* __restrict__ temp,
    const float* __restrict__ addend, float* __restrict__ Ob,
    int T, int tempBase)
{
    extern __shared__ __half smh[];
    const int QS = T + 8;
    __half* Khi = smh;                       // [T][40]
    __half* Klo = Khi + T * 40;
    __half* Vhi = Klo + T * 40;
    __half* Vlo = Vhi + T * 40;
    __half* Qhi = Vlo + T * 40;              // [32][QS]
    __half* Qlo = Qhi + 32 * QS;
    float*  Mv  = (float*)(Qlo + 32 * QS);
    float*  Lv  = Mv + T;
    __half* Pshi = (__half*)(Lv + T);        // NW warps * [16][24]
    __half* Pslo = Pshi + NW * 16 * 24;

    const uint32_t smA   = smem_u32(smh);
    const uint32_t KVoff = (uint32_t)T * 80;
    const uint32_t Qoff  = (uint32_t)32 * QS * 2;

    const int h = blockIdx.x, c = blockIdx.y, b = blockIdx.z;
    const int tid = threadIdx.x, lane = tid & 31, wid = tid >> 5;
    const int qr = lane >> 2, qc = lane & 3;
    const uint32_t ro = (lane & 7) + ((lane >> 3) & 1) * 8;
    const uint32_t co = (lane >> 4) * 8;
    const size_t off = (size_t)b * (T_*D_) + (size_t)c * (128*D_) + (size_t)h * 32 * T;
    const float scale = temp[(tempBase + c) * H_ + h];

    for (int idx = tid; idx < 32 * T; idx += NW * 32) {
        int i = idx / T, t = idx - i * T;
        Khi[t*40 + i] = Kbh[off + idx];
        Klo[t*40 + i] = Kbl[off + idx];
        Vhi[t*40 + i] = Vbh[off + idx];
        Vlo[t*40 + i] = Vbl[off + idx];
        Qhi[i*QS + t] = Qbh[off + idx];
        Qlo[i*QS + t] = Qbl[off + idx];
    }
    __syncthreads();

    const int nb = T >> 4;
    const uint32_t KhiA = smA;
    const uint32_t VhiA = smA + 2 * KVoff;
    const uint32_t QhiA = smA + 4 * KVoff;

    // ---------------- Pass 1: row stats ----------------
    for (int tb = wid; tb < nb; tb += NW) {
        const int t0 = tb * 16;
        unsigned ah[2][4], al[2][4];
#pragma unroll
        for (int ks = 0; ks < 2; ks++) {
            uint32_t ra = KhiA + (((uint32_t)t0 + ro) * 40 + ks*16 + co) * 2;
            ldsm4(ah[ks], ra);
            ldsm4(al[ks], ra + KVoff);
        }
        float m0 = -3.0e38f, m1 = -3.0e38f, l0 = 0.f, l1 = 0.f;
        for (int s0 = 0; s0 < T; s0 += 64) {
            float cc[8][4];
#pragma unroll
            for (int nt = 0; nt < 8; nt++)
#pragma unroll
                for (int j = 0; j < 4; j++) cc[nt][j] = 0.f;
#pragma unroll
            for (int ks = 0; ks < 2; ks++) {
#pragma unroll
                for (int p = 0; p < 4; p++) {
                    uint32_t rv = VhiA + (((uint32_t)(s0 + p*16) + ro) * 40 + ks*16 + co) * 2;
                    unsigned vh4[4], vl4[4];
                    ldsm4(vh4, rv);
                    ldsm4(vl4, rv + KVoff);
                    // rotated: hh pair, hl pair, lh pair (same-acc distance 2)
                    mma_f16(cc[2*p],   ah[ks], vh4[0], vh4[2]);
                    mma_f16(cc[2*p+1], ah[ks], vh4[1], vh4[3]);
                    mma_f16(cc[2*p],   ah[ks], vl4[0], vl4[2]);
                    mma_f16(cc[2*p+1], ah[ks], vl4[1], vl4[3]);
                    mma_f16(cc[2*p],   al[ks], vh4[0], vh4[2]);
                    mma_f16(cc[2*p+1], al[ks], vh4[1], vh4[3]);
                }
            }
            float cm0 = -3.0e38f, cm1 = -3.0e38f;
#pragma unroll
            for (int nt = 0; nt < 8; nt++) {
#pragma unroll
                for (int j = 0; j < 4; j++) cc[nt][j] *= scale;
                cm0 = fmaxf(cm0, fmaxf(cc[nt][0], cc[nt][1]));
                cm1 = fmaxf(cm1, fmaxf(cc[nt][2], cc[nt][3]));
            }
            cm0 = fmaxf(cm0, __shfl_xor_sync(0xffffffffu, cm0, 1));
            cm0 = fmaxf(cm0, __shfl_xor_sync(0xffffffffu, cm0, 2));
            cm1 = fmaxf(cm1, __shfl_xor_sync(0xffffffffu, cm1, 1));
            cm1 = fmaxf(cm1, __shfl_xor_sync(0xffffffffu, cm1, 2));
            float M0 = fmaxf(m0, cm0), M1 = fmaxf(m1, cm1);
            float p0 = 0.f, p1 = 0.f;
#pragma unroll
            for (int nt = 0; nt < 8; nt++) {
                p0 += __expf(cc[nt][0] - M0) + __expf(cc[nt][1] - M0);
                p1 += __expf(cc[nt][2] - M1) + __expf(cc[nt][3] - M1);
            }
            p0 += __shfl_xor_sync(0xffffffffu, p0, 1);
            p0 += __shfl_xor_sync(0xffffffffu, p0, 2);
            p1 += __shfl_xor_sync(0xffffffffu, p1, 1);
            p1 += __shfl_xor_sync(0xffffffffu, p1, 2);
            l0 = l0 * __expf(m0 - M0) + p0;  m0 = M0;
            l1 = l1 * __expf(m1 - M1) + p1;  m1 = M1;
        }
        if (qc == 0) {
            Mv[t0 + qr]     = m0;  Lv[t0 + qr]     = 1.f / l0;
            Mv[t0 + qr + 8] = m1;  Lv[t0 + qr + 8] = 1.f / l1;
        }
    }
    __syncthreads();

    // ---------------- Pass 2: output ----------------
    __half* Pwh = Pshi + wid * (16 * 24);
    __half* Pwl = Pslo + wid * (16 * 24);
    const uint32_t PwhA = smem_u32(Pwh);
    const uint32_t PwlA = smem_u32(Pwl);
    for (int sb = wid; sb < nb; sb += NW) {
        const int s0 = sb * 16;
        unsigned vh[2][4], vl[2][4];
#pragma unroll
        for (int ks = 0; ks < 2; ks++) {
            uint32_t rv = VhiA + (((uint32_t)s0 + ro) * 40 + ks*16 + co) * 2;
            ldsm4(vh[ks], rv);
            ldsm4(vl[ks], rv + KVoff);
        }
        float o[4][4];
#pragma unroll
        for (int ni = 0; ni < 4; ni++)
#pragma unroll
            for (int j = 0; j < 4; j++) o[ni][j] = 0.f;

        for (int t0 = 0; t0 < T; t0 += 16) {
            float e[2][4];
#pragma unroll
            for (int nt = 0; nt < 2; nt++)
#pragma unroll
                for (int j = 0; j < 4; j++) e[nt][j] = 0.f;
#pragma unroll
            for (int ks = 0; ks < 2; ks++) {
                uint32_t rk = KhiA + (((uint32_t)t0 + ro) * 40 + ks*16 + co) * 2;
                unsigned kh4[4], kl4[4];
                ldsm4(kh4, rk);
                ldsm4(kl4, rk + KVoff);
                // rotated: hh pair, hl pair, lh pair
                mma_f16(e[0], vh[ks], kh4[0], kh4[2]);
                mma_f16(e[1], vh[ks], kh4[1], kh4[3]);
                mma_f16(e[0], vh[ks], kl4[0], kl4[2]);
                mma_f16(e[1], vh[ks], kl4[1], kl4[3]);
                mma_f16(e[0], vl[ks], kh4[0], kh4[2]);
                mma_f16(e[1], vl[ks], kh4[1], kh4[3]);
            }
            __syncwarp();
#pragma unroll
            for (int nt = 0; nt < 2; nt++) {
                int tc = t0 + nt * 8 + 2 * qc;
                float mva = Mv[tc],   lva = Lv[tc];
                float mvb = Mv[tc+1], lvb = Lv[tc+1];
                float e0 = __expf(e[nt][0] * scale - mva) * lva;
                float e1 = __expf(e[nt][1] * scale - mvb) * lvb;
                float e2 = __expf(e[nt][2] * scale - mva) * lva;
                float e3 = __expf(e[nt][3] * scale - mvb) * lvb;
                __half h0, h1, h2, h3, g0, g1, g2, g3;
                split_h(e0, h0, g0); split_h(e1, h1, g1);
                split_h(e2, h2, g2); split_h(e3, h3, g3);
                *(unsigned*)(Pwh + qr*24     + nt*8 + 2*qc) = pack2(h0, h1);
                *(unsigned*)(Pwh + (qr+8)*24 + nt*8 + 2*qc) = pack2(h2, h3);
                *(unsigned*)(Pwl + qr*24     + nt*8 + 2*qc) = pack2(g0, g1);
                *(unsigned*)(Pwl + (qr+8)*24 + nt*8 + 2*qc) = pack2(g2, g3);
            }
            __syncwarp();
            unsigned ph[4], pl[4];
            ldsm4(ph, PwhA + (ro*24 + co) * 2);
            ldsm4(pl, PwlA + (ro*24 + co) * 2);
#pragma unroll
            for (int p2 = 0; p2 < 2; p2++) {
                uint32_t rq = QhiA + ((p2*16 + ro) * (uint32_t)QS + (uint32_t)t0 + co) * 2;
                unsigned q4[4], q4l[4];
                ldsm4(q4,  rq);
                ldsm4(q4l, rq + Qoff);
                // rotated: hh pair, hl pair, lh pair
                mma_f16(o[2*p2],   ph, q4[0], q4[2]);
                mma_f16(o[2*p2+1], ph, q4[1], q4[3]);
                mma_f16(o[2*p2],   ph, q4l[0], q4l[2]);
                mma_f16(o[2*p2+1], ph, q4l[1], q4l[3]);
                mma_f16(o[2*p2],   pl, q4[0], q4[2]);
                mma_f16(o[2*p2+1], pl, q4[1], q4[3]);
            }
        }
#pragma unroll
        for (int ni = 0; ni < 4; ni++) {
            int icol = ni * 8 + 2 * qc;
            int srow = s0 + qr;
            size_t base = off + (size_t)icol * T + srow;
            if (addend != nullptr) {
                Ob[base]         = o[ni][0] + addend[base];
                Ob[base + T]     = o[ni][1] + addend[base + T];
                Ob[base + 8]     = o[ni][2] + addend[base + 8];
                Ob[base + T + 8] = o[ni][3] + addend[base + T + 8];
            } else {
                Ob[base]         = o[ni][0];
                Ob[base + T]     = o[ni][1];
                Ob[base + 8]     = o[ni][2];
                Ob[base + T + 8] = o[ni][3];
            }
        }
    }
}

// ---------------------------------------------------------------------------
// LayerNorm: one warp per 512-wide row; emits split fp16 directly.
// ---------------------------------------------------------------------------
__global__ __launch_bounds__(256) void ln_kernel(
    const float* __restrict__ X, const float* __restrict__ gw,
    const float* __restrict__ gb, __half* __restrict__ Yh, __half* __restrict__ Yl)
{
    const int row  = blockIdx.x * 8 + (threadIdx.x >> 5);
    const int lane = threadIdx.x & 31;
    const float4* xr = (const float4*)(X + (size_t)row * D_);
    float4 v[4];
    float s = 0.f, ss = 0.f;
#pragma unroll
    for (int w = 0; w < 4; w++) {
        v[w] = xr[w*32 + lane];
        s  += v[w].x + v[w].y + v[w].z + v[w].w;
        ss += v[w].x*v[w].x + v[w].y*v[w].y + v[w].z*v[w].z + v[w].w*v[w].w;
    }
#pragma unroll
    for (int o = 16; o > 0; o >>= 1) {
        s  += __shfl_xor_sync(0xffffffffu, s, o);
        ss += __shfl_xor_sync(0xffffffffu, ss, o);
    }
    const float mean = s * (1.f/512.f);
    const float var  = ss * (1.f/512.f) - mean*mean;
    const float r = rsqrtf(var + 1e-5f);
    const float4* gr = (const float4*)gw;
    const float4* br = (const float4*)gb;
#pragma unroll
    for (int w = 0; w < 4; w++) {
        float4 gv = gr[w*32 + lane];
        float4 bv = br[w*32 + lane];
        float o0 = (v[w].x - mean) * r * gv.x + bv.x;
        float o1 = (v[w].y - mean) * r * gv.y + bv.y;
        float o2 = (v[w].z - mean) * r * gv.z + bv.z;
        float o3 = (v[w].w - mean) * r * gv.w + bv.w;
        __half h0,h1,h2,h3,l0,l1,l2,l3;
        split_h(o0,h0,l0); split_h(o1,h1,l1); split_h(o2,h2,l2); split_h(o3,h3,l3);
        size_t idx = (size_t)row * D_ + (w*32 + lane) * 4;
        *(uint2*)(Yh + idx) = make_uint2(pack2(h0,h1), pack2(h2,h3));
        *(uint2*)(Yl + idx) = make_uint2(pack2(l0,l1), pack2(l2,l3));
    }
}

// ---------------------------------------------------------------------------
// Combine: out = t1*sig(ld) + t2*(1-sig(ld)), ld = (t1-t2)@fw^T (bias cancels)
// ---------------------------------------------------------------------------
__global__ __launch_bounds__(256) void fuse2_kernel(
    const float4* __restrict__ t1, const float4* __restrict__ t2,
    const float4* __restrict__ ld, float4* __restrict__ out)
{
    int i = blockIdx.x * 256 + threadIdx.x;
    float4 x1 = t1[i], x2 = t2[i], d = ld[i];
    float a0 = 1.f / (1.f + __expf(-d.x));
    float a1 = 1.f / (1.f + __expf(-d.y));
    float a2 = 1.f / (1.f + __expf(-d.z));
    float a3 = 1.f / (1.f + __expf(-d.w));
    float4 o;
    o.x = x1.x * a0 + x2.x * (1.f - a0);
    o.y = x1.y * a1 + x2.y * (1.f - a1);
    o.z = x1.z * a2 + x2.z * (1.f - a2);
    o.w = x1.w * a3 + x2.w * (1.f - a3);
    out[i] = o;
}

// ---------------------------------------------------------------------------
extern "C" void kernel_launch(void* const* d_in, const int* in_sizes, int n_in,
                              void* d_out, int out_size)
{
    (void)in_sizes; (void)n_in; (void)out_size;
    const float* x    = (const float*)d_in[0];
    const float* qw   = (const float*)d_in[1];
    const float* qb   = (const float*)d_in[2];
    const float* kw   = (const float*)d_in[3];
    const float* kb   = (const float*)d_in[4];
    const float* vw   = (const float*)d_in[5];
    const float* vb   = (const float*)d_in[6];
    const float* temp = (const float*)d_in[7];
    const float* lng  = (const float*)d_in[8];
    const float* lnb  = (const float*)d_in[9];
    const float* fw   = (const float*)d_in[10];
    (void)d_in[11];
    float* out = (float*)d_out;

    float *xr, *t1, *t2, *a1;
    __half *qh,*ql,*kh2,*kl2,*vh2,*vl2, *q2h,*q2l,*k2h,*k2l,*v2h,*v2l;
    __half *xh, *xl, *lnh, *lnl, *dh, *dl, *wh, *wl;
    cudaGetSymbolAddress((void**)&xr, g_xr);
    cudaGetSymbolAddress((void**)&t1, g_t1);
    cudaGetSymbolAddress((void**)&t2, g_t2);
    cudaGetSymbolAddress((void**)&a1, g_a1);
    cudaGetSymbolAddress((void**)&qh, g_qh);   cudaGetSymbolAddress((void**)&ql, g_ql);
    cudaGetSymbolAddress((void**)&kh2, g_kh);  cudaGetSymbolAddress((void**)&kl2, g_kl);
    cudaGetSymbolAddress((void**)&vh2, g_vh);  cudaGetSymbolAddress((void**)&vl2, g_vl);
    cudaGetSymbolAddress((void**)&q2h, g_q2h); cudaGetSymbolAddress((void**)&q2l, g_q2l);
    cudaGetSymbolAddress((void**)&k2h, g_k2h); cudaGetSymbolAddress((void**)&k2l, g_k2l);
    cudaGetSymbolAddress((void**)&v2h, g_v2h); cudaGetSymbolAddress((void**)&v2l, g_v2l);
    cudaGetSymbolAddress((void**)&xh, g_xh);   cudaGetSymbolAddress((void**)&xl, g_xl);
    cudaGetSymbolAddress((void**)&lnh, g_lnh); cudaGetSymbolAddress((void**)&lnl, g_lnl);
    cudaGetSymbolAddress((void**)&dh, g_dh);   cudaGetSymbolAddress((void**)&dl, g_dl);
    cudaGetSymbolAddress((void**)&wh, g_wh);   cudaGetSymbolAddress((void**)&wl, g_wl);

    const int gemmSmem = 3 * STAGE_B;                                            // 184320
    const int smem384 = (4*384*40 + 2*32*392) * 2 + 2*384*4 + (2*24*16*24) * 2;  // 212992
    const int smem128 = (4*128*40 + 2*32*136) * 2 + 2*128*4 + (2*8*16*24) * 2;   // 71680
    cudaFuncSetAttribute(gemm_tc, cudaFuncAttributeMaxDynamicSharedMemorySize, gemmSmem);
    cudaFuncSetAttribute(attn_tc<24>, cudaFuncAttributeMaxDynamicSharedMemorySize, smem384);
    cudaFuncSetAttribute(attn_tc<8>,  cudaFuncAttributeMaxDynamicSharedMemorySize, smem128);

    // 1) pre-split x and all weight matrices
    SpArgs sp1;
    sp1.e[0] = { x,  xh,          xl,          BTD    };
    sp1.e[1] = { qw, wh + 0,      wl + 0,      5*WKN  };
    sp1.e[2] = { kw, wh + (size_t)5*WKN,  wl + (size_t)5*WKN,  5*WKN  };
    sp1.e[3] = { vw, wh + (size_t)10*WKN, wl + (size_t)10*WKN, 5*WKN  };
    sp1.e[4] = { fw, wh + (size_t)15*WKN, wl + (size_t)15*WKN, WKN    };
    split_kernel<<<dim3(512, 1, 5), 256>>>(sp1);

    // 2) QKV GEMMs; Q projections single-fp16 (error enters output linearly)
    G5Args ga1;
    ga1.s[0] = { xh, xl, 0,  0, qb, nullptr, qh,  ql,  0, 0 };
    ga1.s[1] = { xh, xl, 5,  0, kb, nullptr, kh2, kl2, 0, 1 };
    ga1.s[2] = { xh, xl, 10, 0, vb, nullptr, vh2, vl2, 0, 1 };
    ga1.s[3] = { xh, xl, 0,  0, qb, nullptr, q2h, q2l, 1, 0 };
    ga1.s[4] = { xh, xl, 5,  0, kb, nullptr, k2h, k2l, 1, 1 };
    ga1.s[5] = { xh, xl, 10, 0, vb, nullptr, v2h, v2l, 1, 1 };
    gemm_tc<<<dim3(2, 96, 6), 512, gemmSmem>>>(ga1);

    attn_tc<24><<<dim3(H_, 1, B_), 768, smem384>>>(qh, ql, kh2, kl2, vh2, vl2, temp, nullptr, xr, 384, 0);
    attn_tc<8><<<dim3(H_, 3, B_), 256, smem128>>>(q2h, q2l, k2h, k2l, v2h, v2l, temp, xr, t1, 128, 1);

    // 3) LayerNorm(t1) -> split fp16
    ln_kernel<<<M_/8, 256>>>(t1, lng, lnb, lnh, lnl);

    // 4) block4 QKV on LN output (reuse half buffers)
    G5Args ga2;
    ga2.s[0] = { lnh, lnl, 0,  4, qb, nullptr, qh,  ql,  0, 0 };
    ga2.s[1] = { lnh, lnl, 5,  4, kb, nullptr, kh2, kl2, 0, 1 };
    ga2.s[2] = { lnh, lnl, 10, 4, vb, nullptr, vh2, vl2, 0, 1 };
    ga2.s[3] = ga2.s[0]; ga2.s[4] = ga2.s[0]; ga2.s[5] = ga2.s[0];
    gemm_tc<<<dim3(2, 96, 3), 512, gemmSmem>>>(ga2);

    attn_tc<24><<<dim3(H_, 1, B_), 768, smem384>>>(qh, ql, kh2, kl2, vh2, vl2, temp, xr, t2, 384, 4);

    // 5) fusion: single GEMM on the difference (bias cancels in softmax)
    diff_split_kernel<<<BTD/4/256, 256>>>((const float4*)t1, (const float4*)t2, dh, dl);
    G5Args ga3;
    ga3.s[0] = { dh, dl, 15, 0, nullptr, a1, nullptr, nullptr, 0, 0 };
    ga3.s[1] = ga3.s[0]; ga3.s[2] = ga3.s[0]; ga3.s[3] = ga3.s[0];
    ga3.s[4] = ga3.s[0]; ga3.s[5] = ga3.s[0];
    gemm_tc<<<dim3(2, 96, 1), 512, gemmSmem>>>(ga3);

    fuse2_kernel<<<BTD/4/256, 256>>>((const float4*)t1, (const float4*)t2,
                                     (const float4*)a1, (float4*)out);
}